// round 6
// baseline (speedup 1.0000x reference)
#include <cuda_runtime.h>
#include <stdint.h>

// ---------------------------------------------------------------------------
// DenseCRF mean-field:
//   * separable spatial Gaussian (z,y,x 1-D convs)
//   * color-sparse bilateral kernel (~17 nbrs/pixel)
// R5: ONE kernel per iteration (reads qOld, writes qNew; no internal sync
//     needed). CTA = (z-slice, y-chunk): z-conv from global, y/x convs in
//     smem with 8-way register blocking, 4-px-interleaved bilateral gather.
// ---------------------------------------------------------------------------

#define NPIX   8192
#define DD     8
#define LL     21
#define LP     24
#define NITER  5
#define NBIN   12
#define NBIN3  1728
#define CAP    128
#define SCAP   2048
#define ECUT   23.0f

#define SA (1.0f/(160.0f*1.41421356237f))
#define SB (1.0f/(3.0f*1.41421356237f))

// ------------------------------- scratch -----------------------------------
__device__ float4 g_col[NPIX];
__device__ int    g_binid[NPIX];
__device__ int    g_binstart[NBIN3];
__device__ int    g_bincnt[NBIN3];
__device__ int    g_binpts[NPIX];
__device__ float2 g_nn[NPIX*CAP];     // (.x = bitcast neighbor idx, .y = kernel)
__device__ int    g_ncnt[NPIX];
__device__ float  g_nbi[NPIX];
__device__ float  g_qA[NPIX*LP];
__device__ float  g_qB[NPIX*LP];
__device__ float  g_CWsp[LL*LL];
__device__ float  g_CWbi[LL*LL];
__device__ float  g_kg[32*32];
__device__ float  g_sz[8];
__device__ float  g_syx[32];

// ---------------------------------------------------------------------------
// Setup: CW matrices, Gaussian LUT + sums, scaled colors, color-bin CSR
// ---------------------------------------------------------------------------
__global__ void k_setup(const float* __restrict__ image,
                        const float* __restrict__ Wsp,
                        const float* __restrict__ Wbi,
                        const float* __restrict__ C)
{
    __shared__ int scnt[NBIN3];
    __shared__ int csum[28];
    const int tid = threadIdx.x;                 // 1024

    for (int e = tid; e < LL*LL; e += 1024) {
        int l = e / LL, m = e - l*LL;
        float a = 0.f, b = 0.f;
        for (int k = 0; k < LL; k++) {
            float c = C[l*LL + k];
            a += c * Wsp[k*LL + m];
            b += c * Wbi[k*LL + m];
        }
        g_CWsp[e] = a; g_CWbi[e] = b;
    }
    {
        int a = tid >> 5, b = tid & 31;
        float d = (float)(a - b) * (1.0f/3.0f);
        g_kg[tid] = __expf(-0.5f * d * d);
    }
    for (int e = tid; e < NBIN3; e += 1024) scnt[e] = 0;
    __syncthreads();

    if (tid < 32) {
        float s = 0.f;
        for (int b = 0; b < 32; b++) s += g_kg[tid*32 + b];
        g_syx[tid] = s;
    } else if (tid < 40) {
        int a = tid - 32;
        float s = 0.f;
        for (int b = 0; b < 8; b++) s += g_kg[a*32 + b];
        g_sz[a] = s;
    }

    for (int i = tid; i < NPIX; i += 1024) {
        float c0 = image[i], c1 = image[NPIX + i], c2 = image[2*NPIX + i];
        g_col[i] = make_float4(c0*SB, c1*SB, c2*SB, 0.f);
        int b0 = (int)(c0 * (12.0f/255.0f)); b0 = b0 < 0 ? 0 : (b0 > 11 ? 11 : b0);
        int b1 = (int)(c1 * (12.0f/255.0f)); b1 = b1 < 0 ? 0 : (b1 > 11 ? 11 : b1);
        int b2 = (int)(c2 * (12.0f/255.0f)); b2 = b2 < 0 ? 0 : (b2 > 11 ? 11 : b2);
        int bin = (b0*NBIN + b1)*NBIN + b2;
        g_binid[i] = bin;
        atomicAdd(&scnt[bin], 1);
    }
    __syncthreads();

    if (tid < 27) {
        int s = 0;
        for (int k = 0; k < 64; k++) s += scnt[tid*64 + k];
        csum[tid] = s;
    }
    __syncthreads();
    if (tid == 0) {
        int s = 0;
        for (int c = 0; c < 27; c++) { int t = csum[c]; csum[c] = s; s += t; }
    }
    __syncthreads();
    for (int b = tid; b < NBIN3; b += 1024) {
        int chunk = b >> 6;
        int s = csum[chunk];
        for (int k = chunk*64; k < b; k++) s += scnt[k];
        g_binstart[b] = s;
        g_bincnt[b]   = scnt[b];
    }
    __syncthreads();
    for (int e = tid; e < NBIN3; e += 1024) scnt[e] = 0;
    __syncthreads();

    // deterministic scatter by warp 0 in fixed pixel order
    if (tid < 32) {
        for (int base = 0; base < NPIX; base += 32) {
            int i = base + tid;
            int b = g_binid[i];
            unsigned m = __match_any_sync(0xffffffffu, b);
            int rank = __popc(m & ((1u << tid) - 1u));
            int leader = __ffs(m) - 1;
            int cur = scnt[b];
            g_binpts[g_binstart[b] + cur + rank] = i;
            __syncwarp();
            if (tid == leader) scnt[b] = cur + __popc(m);
            __syncwarp();
        }
    }
}

// ---------------------------------------------------------------------------
// Build sparse bilateral rows per bin (staged candidate neighborhood).
// ---------------------------------------------------------------------------
__global__ void k_build()
{
    __shared__ int   sj[SCAP];
    __shared__ float s0[SCAP], s1[SCAP], s2[SCAP];
    const int b   = blockIdx.x;
    const int cnt = g_bincnt[b];
    if (cnt == 0) return;

    int b0 = b / 144, r = b - b0*144, b1 = r / 12, b2 = r - b1*12;
    int d0lo = b0 > 0 ? b0-1 : 0, d0hi = b0 < 11 ? b0+1 : 11;
    int d1lo = b1 > 0 ? b1-1 : 0, d1hi = b1 < 11 ? b1+1 : 11;
    int d2lo = b2 > 0 ? b2-1 : 0, d2hi = b2 < 11 ? b2+1 : 11;

    int pos = 0;
    for (int d0 = d0lo; d0 <= d0hi; d0++)
    for (int d1 = d1lo; d1 <= d1hi; d1++)
    for (int d2 = d2lo; d2 <= d2hi; d2++) {
        int nbin = (d0*NBIN + d1)*NBIN + d2;
        int s = g_binstart[nbin], c = g_bincnt[nbin];
        if (pos + c > SCAP) c = SCAP - pos;
        for (int t = threadIdx.x; t < c; t += 128) {
            int j = g_binpts[s + t];
            float4 col = g_col[j];
            sj[pos + t] = j;
            s0[pos + t] = col.x; s1[pos + t] = col.y; s2[pos + t] = col.z;
        }
        pos += c;
    }
    __syncthreads();

    const int lane = threadIdx.x & 31;
    const int w    = threadIdx.x >> 5;
    const int mybase = g_binstart[b];

    for (int p = w; p < cnt; p += 4) {
        int i = g_binpts[mybase + p];
        float4 ci = g_col[i];
        int iz = i >> 10, iy = (i >> 5) & 31, ix = i & 31;
        int   acc = 0;
        float nb  = 0.f;
        for (int base = 0; base < pos; base += 32) {
            int idx = base + lane;
            float ev = 1e30f; int j = 0;
            if (idx < pos) {
                j = sj[idx];
                float dz = (float)(iz - (j >> 10));
                float dy = (float)(iy - ((j >> 5) & 31));
                float dx = (float)(ix - (j & 31));
                float u3 = ci.x - s0[idx];
                float u4 = ci.y - s1[idx];
                float u5 = ci.z - s2[idx];
                ev = (dz*dz + dy*dy + dx*dx) * (SA*SA) + u3*u3 + u4*u4 + u5*u5;
            }
            bool a = (ev <= ECUT);
            unsigned m = __ballot_sync(0xffffffffu, a);
            if (a) {
                int off = acc + __popc(m & ((1u << lane) - 1u));
                if (off < CAP) {
                    float kv = __expf(-ev);
                    g_nn[i*CAP + off] = make_float2(__int_as_float(j), kv);
                    nb += kv;
                }
            }
            acc += __popc(m);
        }
        for (int o = 16; o; o >>= 1) nb += __shfl_xor_sync(0xffffffffu, nb, o);
        if (acc > CAP) acc = CAP;
        if (lane == 0) { g_ncnt[i] = acc; g_nbi[i] = nb; }
    }
}

// ---------------------------------------------------------------------------
__global__ void k_softmax0(const float* __restrict__ logits)
{
    int i = blockIdx.x * blockDim.x + threadIdx.x;
    float v[LL];
    float mx = -1e30f;
    #pragma unroll
    for (int l = 0; l < LL; l++) { v[l] = logits[l*NPIX + i]; mx = fmaxf(mx, v[l]); }
    float s = 0.f;
    #pragma unroll
    for (int l = 0; l < LL; l++) { v[l] = __expf(v[l] - mx); s += v[l]; }
    float inv = 1.0f / s;
    #pragma unroll
    for (int l = 0; l < LL; l++) g_qA[i*LP + l] = v[l] * inv;
    g_qA[i*LP + 21] = 0.f; g_qA[i*LP + 22] = 0.f; g_qA[i*LP + 23] = 0.f;
}

// ---------------------------------------------------------------------------
// One full mean-field iteration. grid = 32 CTAs: (z in [0,8)) x (ychunk [0,4)).
// Reads qin everywhere, writes qout for own 256 pixels only.
// ---------------------------------------------------------------------------
__global__ void __launch_bounds__(1024, 1)
k_iter(const float* __restrict__ qin, float* __restrict__ qout,
       const float* __restrict__ unary, float* __restrict__ out, int last)
{
    extern __shared__ float sm[];
    float* t1   = sm;                 // 24576 floats  (full slice, z-conv out)
    float* tmid = sm + 24576;         // 6144  floats  (my 8 rows, y-conv out)
    float* bn   = sm + 30720;         // 6144  floats  (bilateral, normalized)
    float* sp   = sm;                 // aliases t1 after y-conv consumed it
    __shared__ float s_kg[1024];
    __shared__ float s_w[2*LL*LL];

    const int tid  = threadIdx.x;
    const int lane = tid & 31;
    const int warp = tid >> 5;
    const int z    = blockIdx.x >> 2;
    const int y0   = (blockIdx.x & 3) * 8;

    s_kg[tid] = g_kg[tid];
    if (tid < 2*LL*LL) s_w[tid] = (tid < LL*LL) ? g_CWsp[tid] : g_CWbi[tid - LL*LL];

    // ---- bilateral gather: 8 px per warp, 4 interleaved, float2 pairs ----
    if (lane < LP) {
        for (int g = 0; g < 8; g += 4) {
            int pl[4], i4[4], cnt[4];
            const float2* pp[4];
            float acc[4] = {0.f, 0.f, 0.f, 0.f};
            int mc = 0;
            #pragma unroll
            for (int k = 0; k < 4; k++) {
                pl[k] = warp*8 + g + k;
                i4[k] = (z << 10) | ((y0 + (pl[k] >> 5)) << 5) | (pl[k] & 31);
                cnt[k] = g_ncnt[i4[k]];
                pp[k]  = &g_nn[i4[k]*CAP];
                mc = cnt[k] > mc ? cnt[k] : mc;
            }
            for (int n = 0; n < mc; n += 2) {
                #pragma unroll
                for (int k = 0; k < 4; k++) {
                    #pragma unroll
                    for (int u = 0; u < 2; u++) {
                        if (n + u < cnt[k]) {
                            float2 jk = pp[k][n + u];
                            acc[k] += jk.y * qin[__float_as_int(jk.x)*LP + lane];
                        }
                    }
                }
            }
            #pragma unroll
            for (int k = 0; k < 4; k++)
                bn[pl[k]*LP + lane] = acc[k] / g_nbi[i4[k]];
        }
    }
    __syncthreads();     // covers s_kg/s_w loads + bn writes

    // ---- z-conv: fully linear, coalesced ----
    {
        float kz[DD];
        #pragma unroll
        for (int zp = 0; zp < DD; zp++) kz[zp] = s_kg[z*32 + zp];
        for (int t = tid; t < 24576; t += 1024) {
            float a = 0.f;
            #pragma unroll
            for (int zp = 0; zp < DD; zp++)
                a += kz[zp] * qin[(zp << 10)*LP + t];
            t1[t] = a;
        }
    }
    __syncthreads();

    // ---- y-conv: thread (x,l) for tid<768, 8 outputs blocked in registers ----
    if (tid < 768) {
        int x = tid / LP, l = tid - x*LP;
        float acc[8] = {0,0,0,0,0,0,0,0};
        for (int yp = 0; yp < 32; yp++) {
            float v = t1[(yp*32 + x)*LP + l];
            #pragma unroll
            for (int yy = 0; yy < 8; yy++)
                acc[yy] += s_kg[(y0 + yy)*32 + yp] * v;
        }
        #pragma unroll
        for (int yy = 0; yy < 8; yy++)
            tmid[(yy*32 + x)*LP + l] = acc[yy];
    }
    __syncthreads();

    // ---- x-conv + spatial normalize: thread (yy, xg, l), 8 x-outputs ----
    if (tid < 768) {
        int yy = tid / 96, s = tid - yy*96, xg = s / LP, l = s - xg*LP;
        float acc[8] = {0,0,0,0,0,0,0,0};
        for (int xp = 0; xp < 32; xp++) {
            float v = tmid[(yy*32 + xp)*LP + l];
            #pragma unroll
            for (int xx = 0; xx < 8; xx++)
                acc[xx] += s_kg[(xg*8 + xx)*32 + xp] * v;
        }
        float nzy = g_sz[z] * g_syx[y0 + yy];
        #pragma unroll
        for (int xx = 0; xx < 8; xx++) {
            int x = xg*8 + xx;
            sp[(yy*32 + x)*LP + l] = acc[xx] / (nzy * g_syx[x]);
        }
    }
    __syncthreads();

    // ---- mixing + unary + softmax: warp per pixel (8 px per warp) ----
    for (int g = 0; g < 8; g++) {
        int pl = warp*8 + g;
        int yy = pl >> 5, x = pl & 31;
        int i = (z << 10) | ((y0 + yy) << 5) | x;
        float cur = -1e30f;
        if (lane < LL) {
            float msg = 0.f;
            #pragma unroll
            for (int m = 0; m < LL; m++)
                msg += s_w[lane*LL + m] * sp[pl*LP + m]
                     + s_w[LL*LL + lane*LL + m] * bn[pl*LP + m];
            cur = unary[lane*NPIX + i] + msg;
        }
        float mx = cur;
        #pragma unroll
        for (int o = 16; o; o >>= 1) mx = fmaxf(mx, __shfl_xor_sync(0xffffffffu, mx, o));
        float e = (lane < LL) ? __expf(cur - mx) : 0.f;
        float se = e;
        #pragma unroll
        for (int o = 16; o; o >>= 1) se += __shfl_xor_sync(0xffffffffu, se, o);
        float q = e / se;
        if (lane < LP) qout[i*LP + lane] = (lane < LL) ? q : 0.f;
        if (last && lane < LL) out[lane*NPIX + i] = q;
    }
}

// ---------------------------------------------------------------------------
extern "C" void kernel_launch(void* const* d_in, const int* in_sizes, int n_in,
                              void* d_out, int out_size)
{
    (void)in_sizes; (void)n_in; (void)out_size;
    const float* image  = (const float*)d_in[0];
    const float* logits = (const float*)d_in[1];
    const float* unary  = (const float*)d_in[2];
    const float* Wsp    = (const float*)d_in[3];
    const float* Wbi    = (const float*)d_in[4];
    const float* C      = (const float*)d_in[5];
    float* out = (float*)d_out;

    const int DSMEM = 36864 * (int)sizeof(float);   // 147456 B
    cudaFuncSetAttribute(k_iter, cudaFuncAttributeMaxDynamicSharedMemorySize, DSMEM);

    k_setup<<<1, 1024>>>(image, Wsp, Wbi, C);
    k_build<<<NBIN3, 128>>>();
    k_softmax0<<<64, 128>>>(logits);

    float* qa; float* qb;
    cudaGetSymbolAddress((void**)&qa, g_qA);
    cudaGetSymbolAddress((void**)&qb, g_qB);
    for (int it = 0; it < NITER; it++) {
        const float* qi = (it & 1) ? qb : qa;
        float*       qo = (it & 1) ? qa : qb;
        k_iter<<<32, 1024, DSMEM>>>(qi, qo, unary, out, it == NITER - 1);
    }
}

// round 7
// speedup vs baseline: 1.0056x; 1.0056x over previous
#include <cuda_runtime.h>
#include <stdint.h>

// ---------------------------------------------------------------------------
// DenseCRF mean-field:
//   * separable spatial Gaussian (z,y,x 1-D convs)
//   * color-sparse bilateral kernel (~17 nbrs/pixel)
// R5: ONE kernel per iteration (reads qOld, writes qNew; no internal sync
//     needed). CTA = (z-slice, y-chunk): z-conv from global, y/x convs in
//     smem with 8-way register blocking, 4-px-interleaved bilateral gather.
// ---------------------------------------------------------------------------

#define NPIX   8192
#define DD     8
#define LL     21
#define LP     24
#define NITER  5
#define NBIN   12
#define NBIN3  1728
#define CAP    128
#define SCAP   2048
#define ECUT   23.0f

#define SA (1.0f/(160.0f*1.41421356237f))
#define SB (1.0f/(3.0f*1.41421356237f))

// ------------------------------- scratch -----------------------------------
__device__ float4 g_col[NPIX];
__device__ int    g_binid[NPIX];
__device__ int    g_binstart[NBIN3];
__device__ int    g_bincnt[NBIN3];
__device__ int    g_binpts[NPIX];
__device__ float2 g_nn[NPIX*CAP];     // (.x = bitcast neighbor idx, .y = kernel)
__device__ int    g_ncnt[NPIX];
__device__ float  g_nbi[NPIX];
__device__ float  g_qA[NPIX*LP];
__device__ float  g_qB[NPIX*LP];
__device__ float  g_CWsp[LL*LL];
__device__ float  g_CWbi[LL*LL];
__device__ float  g_kg[32*32];
__device__ float  g_sz[8];
__device__ float  g_syx[32];

// ---------------------------------------------------------------------------
// Setup: CW matrices, Gaussian LUT + sums, scaled colors, color-bin CSR
// ---------------------------------------------------------------------------
__global__ void k_setup(const float* __restrict__ image,
                        const float* __restrict__ Wsp,
                        const float* __restrict__ Wbi,
                        const float* __restrict__ C)
{
    __shared__ int scnt[NBIN3];
    __shared__ int csum[28];
    const int tid = threadIdx.x;                 // 1024

    for (int e = tid; e < LL*LL; e += 1024) {
        int l = e / LL, m = e - l*LL;
        float a = 0.f, b = 0.f;
        for (int k = 0; k < LL; k++) {
            float c = C[l*LL + k];
            a += c * Wsp[k*LL + m];
            b += c * Wbi[k*LL + m];
        }
        g_CWsp[e] = a; g_CWbi[e] = b;
    }
    {
        int a = tid >> 5, b = tid & 31;
        float d = (float)(a - b) * (1.0f/3.0f);
        g_kg[tid] = __expf(-0.5f * d * d);
    }
    for (int e = tid; e < NBIN3; e += 1024) scnt[e] = 0;
    __syncthreads();

    if (tid < 32) {
        float s = 0.f;
        for (int b = 0; b < 32; b++) s += g_kg[tid*32 + b];
        g_syx[tid] = s;
    } else if (tid < 40) {
        int a = tid - 32;
        float s = 0.f;
        for (int b = 0; b < 8; b++) s += g_kg[a*32 + b];
        g_sz[a] = s;
    }

    for (int i = tid; i < NPIX; i += 1024) {
        float c0 = image[i], c1 = image[NPIX + i], c2 = image[2*NPIX + i];
        g_col[i] = make_float4(c0*SB, c1*SB, c2*SB, 0.f);
        int b0 = (int)(c0 * (12.0f/255.0f)); b0 = b0 < 0 ? 0 : (b0 > 11 ? 11 : b0);
        int b1 = (int)(c1 * (12.0f/255.0f)); b1 = b1 < 0 ? 0 : (b1 > 11 ? 11 : b1);
        int b2 = (int)(c2 * (12.0f/255.0f)); b2 = b2 < 0 ? 0 : (b2 > 11 ? 11 : b2);
        int bin = (b0*NBIN + b1)*NBIN + b2;
        g_binid[i] = bin;
        atomicAdd(&scnt[bin], 1);
    }
    __syncthreads();

    if (tid < 27) {
        int s = 0;
        for (int k = 0; k < 64; k++) s += scnt[tid*64 + k];
        csum[tid] = s;
    }
    __syncthreads();
    if (tid == 0) {
        int s = 0;
        for (int c = 0; c < 27; c++) { int t = csum[c]; csum[c] = s; s += t; }
    }
    __syncthreads();
    for (int b = tid; b < NBIN3; b += 1024) {
        int chunk = b >> 6;
        int s = csum[chunk];
        for (int k = chunk*64; k < b; k++) s += scnt[k];
        g_binstart[b] = s;
        g_bincnt[b]   = scnt[b];
    }
    __syncthreads();
    for (int e = tid; e < NBIN3; e += 1024) scnt[e] = 0;
    __syncthreads();

    // deterministic scatter by warp 0 in fixed pixel order
    if (tid < 32) {
        for (int base = 0; base < NPIX; base += 32) {
            int i = base + tid;
            int b = g_binid[i];
            unsigned m = __match_any_sync(0xffffffffu, b);
            int rank = __popc(m & ((1u << tid) - 1u));
            int leader = __ffs(m) - 1;
            int cur = scnt[b];
            g_binpts[g_binstart[b] + cur + rank] = i;
            __syncwarp();
            if (tid == leader) scnt[b] = cur + __popc(m);
            __syncwarp();
        }
    }
}

// ---------------------------------------------------------------------------
// Build sparse bilateral rows per bin (staged candidate neighborhood).
// ---------------------------------------------------------------------------
__global__ void k_build()
{
    __shared__ int   sj[SCAP];
    __shared__ float s0[SCAP], s1[SCAP], s2[SCAP];
    const int b   = blockIdx.x;
    const int cnt = g_bincnt[b];
    if (cnt == 0) return;

    int b0 = b / 144, r = b - b0*144, b1 = r / 12, b2 = r - b1*12;
    int d0lo = b0 > 0 ? b0-1 : 0, d0hi = b0 < 11 ? b0+1 : 11;
    int d1lo = b1 > 0 ? b1-1 : 0, d1hi = b1 < 11 ? b1+1 : 11;
    int d2lo = b2 > 0 ? b2-1 : 0, d2hi = b2 < 11 ? b2+1 : 11;

    int pos = 0;
    for (int d0 = d0lo; d0 <= d0hi; d0++)
    for (int d1 = d1lo; d1 <= d1hi; d1++)
    for (int d2 = d2lo; d2 <= d2hi; d2++) {
        int nbin = (d0*NBIN + d1)*NBIN + d2;
        int s = g_binstart[nbin], c = g_bincnt[nbin];
        if (pos + c > SCAP) c = SCAP - pos;
        for (int t = threadIdx.x; t < c; t += 128) {
            int j = g_binpts[s + t];
            float4 col = g_col[j];
            sj[pos + t] = j;
            s0[pos + t] = col.x; s1[pos + t] = col.y; s2[pos + t] = col.z;
        }
        pos += c;
    }
    __syncthreads();

    const int lane = threadIdx.x & 31;
    const int w    = threadIdx.x >> 5;
    const int mybase = g_binstart[b];

    for (int p = w; p < cnt; p += 4) {
        int i = g_binpts[mybase + p];
        float4 ci = g_col[i];
        int iz = i >> 10, iy = (i >> 5) & 31, ix = i & 31;
        int   acc = 0;
        float nb  = 0.f;
        for (int base = 0; base < pos; base += 32) {
            int idx = base + lane;
            float ev = 1e30f; int j = 0;
            if (idx < pos) {
                j = sj[idx];
                float dz = (float)(iz - (j >> 10));
                float dy = (float)(iy - ((j >> 5) & 31));
                float dx = (float)(ix - (j & 31));
                float u3 = ci.x - s0[idx];
                float u4 = ci.y - s1[idx];
                float u5 = ci.z - s2[idx];
                ev = (dz*dz + dy*dy + dx*dx) * (SA*SA) + u3*u3 + u4*u4 + u5*u5;
            }
            bool a = (ev <= ECUT);
            unsigned m = __ballot_sync(0xffffffffu, a);
            if (a) {
                int off = acc + __popc(m & ((1u << lane) - 1u));
                if (off < CAP) {
                    float kv = __expf(-ev);
                    g_nn[i*CAP + off] = make_float2(__int_as_float(j), kv);
                    nb += kv;
                }
            }
            acc += __popc(m);
        }
        for (int o = 16; o; o >>= 1) nb += __shfl_xor_sync(0xffffffffu, nb, o);
        if (acc > CAP) acc = CAP;
        if (lane == 0) { g_ncnt[i] = acc; g_nbi[i] = nb; }
    }
}

// ---------------------------------------------------------------------------
__global__ void k_softmax0(const float* __restrict__ logits)
{
    int i = blockIdx.x * blockDim.x + threadIdx.x;
    float v[LL];
    float mx = -1e30f;
    #pragma unroll
    for (int l = 0; l < LL; l++) { v[l] = logits[l*NPIX + i]; mx = fmaxf(mx, v[l]); }
    float s = 0.f;
    #pragma unroll
    for (int l = 0; l < LL; l++) { v[l] = __expf(v[l] - mx); s += v[l]; }
    float inv = 1.0f / s;
    #pragma unroll
    for (int l = 0; l < LL; l++) g_qA[i*LP + l] = v[l] * inv;
    g_qA[i*LP + 21] = 0.f; g_qA[i*LP + 22] = 0.f; g_qA[i*LP + 23] = 0.f;
}

// ---------------------------------------------------------------------------
// One full mean-field iteration. grid = 32 CTAs: (z in [0,8)) x (ychunk [0,4)).
// Reads qin everywhere, writes qout for own 256 pixels only.
// ---------------------------------------------------------------------------
__global__ void __launch_bounds__(1024, 1)
k_iter(const float* __restrict__ qin, float* __restrict__ qout,
       const float* __restrict__ unary, float* __restrict__ out, int last)
{
    extern __shared__ float sm[];
    float* t1   = sm;                 // 24576 floats  (full slice, z-conv out)
    float* tmid = sm + 24576;         // 6144  floats  (my 8 rows, y-conv out)
    float* bn   = sm + 30720;         // 6144  floats  (bilateral, normalized)
    float* sp   = sm;                 // aliases t1 after y-conv consumed it
    __shared__ float s_kg[1024];
    __shared__ float s_w[2*LL*LL];

    const int tid  = threadIdx.x;
    const int lane = tid & 31;
    const int warp = tid >> 5;
    const int z    = blockIdx.x >> 2;
    const int y0   = (blockIdx.x & 3) * 8;

    s_kg[tid] = g_kg[tid];
    if (tid < 2*LL*LL) s_w[tid] = (tid < LL*LL) ? g_CWsp[tid] : g_CWbi[tid - LL*LL];

    // ---- bilateral gather: 8 px per warp, 4 interleaved, float2 pairs ----
    if (lane < LP) {
        for (int g = 0; g < 8; g += 4) {
            int pl[4], i4[4], cnt[4];
            const float2* pp[4];
            float acc[4] = {0.f, 0.f, 0.f, 0.f};
            int mc = 0;
            #pragma unroll
            for (int k = 0; k < 4; k++) {
                pl[k] = warp*8 + g + k;
                i4[k] = (z << 10) | ((y0 + (pl[k] >> 5)) << 5) | (pl[k] & 31);
                cnt[k] = g_ncnt[i4[k]];
                pp[k]  = &g_nn[i4[k]*CAP];
                mc = cnt[k] > mc ? cnt[k] : mc;
            }
            for (int n = 0; n < mc; n += 2) {
                #pragma unroll
                for (int k = 0; k < 4; k++) {
                    #pragma unroll
                    for (int u = 0; u < 2; u++) {
                        if (n + u < cnt[k]) {
                            float2 jk = pp[k][n + u];
                            acc[k] += jk.y * qin[__float_as_int(jk.x)*LP + lane];
                        }
                    }
                }
            }
            #pragma unroll
            for (int k = 0; k < 4; k++)
                bn[pl[k]*LP + lane] = acc[k] / g_nbi[i4[k]];
        }
    }
    __syncthreads();     // covers s_kg/s_w loads + bn writes

    // ---- z-conv: fully linear, coalesced ----
    {
        float kz[DD];
        #pragma unroll
        for (int zp = 0; zp < DD; zp++) kz[zp] = s_kg[z*32 + zp];
        for (int t = tid; t < 24576; t += 1024) {
            float a = 0.f;
            #pragma unroll
            for (int zp = 0; zp < DD; zp++)
                a += kz[zp] * qin[(zp << 10)*LP + t];
            t1[t] = a;
        }
    }
    __syncthreads();

    // ---- y-conv: thread (x,l) for tid<768, 8 outputs blocked in registers ----
    if (tid < 768) {
        int x = tid / LP, l = tid - x*LP;
        float acc[8] = {0,0,0,0,0,0,0,0};
        for (int yp = 0; yp < 32; yp++) {
            float v = t1[(yp*32 + x)*LP + l];
            #pragma unroll
            for (int yy = 0; yy < 8; yy++)
                acc[yy] += s_kg[(y0 + yy)*32 + yp] * v;
        }
        #pragma unroll
        for (int yy = 0; yy < 8; yy++)
            tmid[(yy*32 + x)*LP + l] = acc[yy];
    }
    __syncthreads();

    // ---- x-conv + spatial normalize: thread (yy, xg, l), 8 x-outputs ----
    if (tid < 768) {
        int yy = tid / 96, s = tid - yy*96, xg = s / LP, l = s - xg*LP;
        float acc[8] = {0,0,0,0,0,0,0,0};
        for (int xp = 0; xp < 32; xp++) {
            float v = tmid[(yy*32 + xp)*LP + l];
            #pragma unroll
            for (int xx = 0; xx < 8; xx++)
                acc[xx] += s_kg[(xg*8 + xx)*32 + xp] * v;
        }
        float nzy = g_sz[z] * g_syx[y0 + yy];
        #pragma unroll
        for (int xx = 0; xx < 8; xx++) {
            int x = xg*8 + xx;
            sp[(yy*32 + x)*LP + l] = acc[xx] / (nzy * g_syx[x]);
        }
    }
    __syncthreads();

    // ---- mixing + unary + softmax: warp per pixel (8 px per warp) ----
    for (int g = 0; g < 8; g++) {
        int pl = warp*8 + g;
        int yy = pl >> 5, x = pl & 31;
        int i = (z << 10) | ((y0 + yy) << 5) | x;
        float cur = -1e30f;
        if (lane < LL) {
            float msg = 0.f;
            #pragma unroll
            for (int m = 0; m < LL; m++)
                msg += s_w[lane*LL + m] * sp[pl*LP + m]
                     + s_w[LL*LL + lane*LL + m] * bn[pl*LP + m];
            cur = unary[lane*NPIX + i] + msg;
        }
        float mx = cur;
        #pragma unroll
        for (int o = 16; o; o >>= 1) mx = fmaxf(mx, __shfl_xor_sync(0xffffffffu, mx, o));
        float e = (lane < LL) ? __expf(cur - mx) : 0.f;
        float se = e;
        #pragma unroll
        for (int o = 16; o; o >>= 1) se += __shfl_xor_sync(0xffffffffu, se, o);
        float q = e / se;
        if (lane < LP) qout[i*LP + lane] = (lane < LL) ? q : 0.f;
        if (last && lane < LL) out[lane*NPIX + i] = q;
    }
}

// ---------------------------------------------------------------------------
extern "C" void kernel_launch(void* const* d_in, const int* in_sizes, int n_in,
                              void* d_out, int out_size)
{
    (void)in_sizes; (void)n_in; (void)out_size;
    const float* image  = (const float*)d_in[0];
    const float* logits = (const float*)d_in[1];
    const float* unary  = (const float*)d_in[2];
    const float* Wsp    = (const float*)d_in[3];
    const float* Wbi    = (const float*)d_in[4];
    const float* C      = (const float*)d_in[5];
    float* out = (float*)d_out;

    const int DSMEM = 36864 * (int)sizeof(float);   // 147456 B
    cudaFuncSetAttribute(k_iter, cudaFuncAttributeMaxDynamicSharedMemorySize, DSMEM);

    k_setup<<<1, 1024>>>(image, Wsp, Wbi, C);
    k_build<<<NBIN3, 128>>>();
    k_softmax0<<<64, 128>>>(logits);

    float* qa; float* qb;
    cudaGetSymbolAddress((void**)&qa, g_qA);
    cudaGetSymbolAddress((void**)&qb, g_qB);
    for (int it = 0; it < NITER; it++) {
        const float* qi = (it & 1) ? qb : qa;
        float*       qo = (it & 1) ? qa : qb;
        k_iter<<<32, 1024, DSMEM>>>(qi, qo, unary, out, it == NITER - 1);
    }
}

// round 8
// speedup vs baseline: 2.2417x; 2.2292x over previous
#include <cuda_runtime.h>
#include <stdint.h>

// ---------------------------------------------------------------------------
// DenseCRF mean-field (R5):
//   * separable spatial Gaussian (3 x 1-D convs)         [R2 structure kept]
//   * color-sparse bilateral kernel (~17 nbrs/pixel)
//   * setup fully parallelized (atomic scatter + per-bin sort -> deterministic)
//   * unary transposed once -> linear reads in k_final
// ---------------------------------------------------------------------------

#define NPIX   8192
#define DD     8
#define LL     21
#define LP     24
#define NITER  5
#define NBIN   12
#define NBIN3  1728
#define CAP    128
#define SCAP   2048
#define ECUT   23.0f

#define SA (1.0f/(160.0f*1.41421356237f))
#define SB (1.0f/(3.0f*1.41421356237f))

// ------------------------------- scratch -----------------------------------
__device__ float4 g_col[NPIX];
__device__ int    g_binid[NPIX];
__device__ int    g_binstart[NBIN3];
__device__ int    g_bincnt[NBIN3];
__device__ int    g_bincur[NBIN3];
__device__ int    g_binpts[NPIX];
__device__ float2 g_nn[NPIX*CAP];     // (.x = bitcast idx, .y = kernel value)
__device__ int    g_ncnt[NPIX];
__device__ float  g_nbi[NPIX];
__device__ float  g_qT[NPIX*LP];
__device__ float  g_uT[NPIX*LP];      // unary transposed, pixel-major
__device__ float  g_t1[NPIX*LP];
__device__ float  g_t2[NPIX*LP];
__device__ float  g_bi[NPIX*LP];
__device__ float  g_CWsp[LL*LL];
__device__ float  g_CWbi[LL*LL];
__device__ float  g_kg[32*32];
__device__ float  g_sz[8];
__device__ float  g_syx[32];

// ---------------------------------------------------------------------------
__global__ void k_prep(const float* __restrict__ image,
                       const float* __restrict__ logits,
                       const float* __restrict__ unary)
{
    int i = blockIdx.x * blockDim.x + threadIdx.x;    // 8192
    float c0 = image[i], c1 = image[NPIX + i], c2 = image[2*NPIX + i];
    g_col[i] = make_float4(c0*SB, c1*SB, c2*SB, 0.f);
    int b0 = (int)(c0 * (12.0f/255.0f)); b0 = b0 < 0 ? 0 : (b0 > 11 ? 11 : b0);
    int b1 = (int)(c1 * (12.0f/255.0f)); b1 = b1 < 0 ? 0 : (b1 > 11 ? 11 : b1);
    int b2 = (int)(c2 * (12.0f/255.0f)); b2 = b2 < 0 ? 0 : (b2 > 11 ? 11 : b2);
    int bin = (b0*NBIN + b1)*NBIN + b2;
    g_binid[i] = bin;
    atomicAdd(&g_bincnt[bin], 1);

    float v[LL]; float mx = -1e30f;
    #pragma unroll
    for (int l = 0; l < LL; l++) { v[l] = logits[l*NPIX + i]; mx = fmaxf(mx, v[l]); }
    float s = 0.f;
    #pragma unroll
    for (int l = 0; l < LL; l++) { v[l] = __expf(v[l] - mx); s += v[l]; }
    float inv = 1.0f / s;
    #pragma unroll
    for (int l = 0; l < LL; l++) g_qT[i*LP + l] = v[l] * inv;
    g_qT[i*LP + 21] = 0.f; g_qT[i*LP + 22] = 0.f; g_qT[i*LP + 23] = 0.f;

    #pragma unroll
    for (int l = 0; l < LL; l++) g_uT[i*LP + l] = unary[l*NPIX + i];
}

// ---------------------------------------------------------------------------
__global__ void k_scan(const float* __restrict__ Wsp,
                       const float* __restrict__ Wbi,
                       const float* __restrict__ C)
{
    __shared__ int scnt[NBIN3];
    __shared__ int csum[28];
    const int tid = threadIdx.x;                 // 1024

    for (int e = tid; e < LL*LL; e += 1024) {
        int l = e / LL, m = e - l*LL;
        float a = 0.f, b = 0.f;
        for (int k = 0; k < LL; k++) {
            float c = C[l*LL + k];
            a += c * Wsp[k*LL + m];
            b += c * Wbi[k*LL + m];
        }
        g_CWsp[e] = a; g_CWbi[e] = b;
    }
    {
        int a = tid >> 5, b = tid & 31;
        float d = (float)(a - b) * (1.0f/3.0f);
        g_kg[tid] = __expf(-0.5f * d * d);
    }
    if (tid < 32) {
        float s = 0.f;
        for (int b = 0; b < 32; b++) { float d = (float)(tid-b)*(1.0f/3.0f); s += __expf(-0.5f*d*d); }
        g_syx[tid] = s;
    } else if (tid < 40) {
        int a = tid - 32; float s = 0.f;
        for (int b = 0; b < 8; b++) { float d = (float)(a-b)*(1.0f/3.0f); s += __expf(-0.5f*d*d); }
        g_sz[a] = s;
    }
    for (int e = tid; e < NBIN3; e += 1024) scnt[e] = g_bincnt[e];
    __syncthreads();
    if (tid < 27) {
        int s = 0;
        for (int k = 0; k < 64; k++) s += scnt[tid*64 + k];
        csum[tid] = s;
    }
    __syncthreads();
    if (tid == 0) {
        int s = 0;
        for (int c = 0; c < 27; c++) { int t = csum[c]; csum[c] = s; s += t; }
    }
    __syncthreads();
    for (int b = tid; b < NBIN3; b += 1024) {
        int chunk = b >> 6;
        int s = csum[chunk];
        for (int k = chunk*64; k < b; k++) s += scnt[k];
        g_binstart[b] = s;
    }
}

// ---------------------------------------------------------------------------
__global__ void k_scatter()
{
    int i = blockIdx.x * blockDim.x + threadIdx.x;    // 8192
    int b = g_binid[i];
    int off = atomicAdd(&g_bincur[b], 1);
    g_binpts[g_binstart[b] + off] = i;
}

// per-bin ascending insertion sort -> deterministic CSR order
__global__ void k_sortbins()
{
    int b = blockIdx.x * blockDim.x + threadIdx.x;
    if (b >= NBIN3) return;
    int s = g_binstart[b], c = g_bincnt[b];
    for (int a = 1; a < c; a++) {
        int v = g_binpts[s + a]; int k = a - 1;
        while (k >= 0 && g_binpts[s + k] > v) { g_binpts[s + k + 1] = g_binpts[s + k]; k--; }
        g_binpts[s + k + 1] = v;
    }
}

// ---------------------------------------------------------------------------
__global__ void k_build()
{
    __shared__ int   sj[SCAP];
    __shared__ float s0[SCAP], s1[SCAP], s2[SCAP];
    const int b   = blockIdx.x;
    const int cnt = g_bincnt[b];
    if (cnt == 0) return;

    int b0 = b / 144, r = b - b0*144, b1 = r / 12, b2 = r - b1*12;
    int d0lo = b0 > 0 ? b0-1 : 0, d0hi = b0 < 11 ? b0+1 : 11;
    int d1lo = b1 > 0 ? b1-1 : 0, d1hi = b1 < 11 ? b1+1 : 11;
    int d2lo = b2 > 0 ? b2-1 : 0, d2hi = b2 < 11 ? b2+1 : 11;

    int pos = 0;
    for (int d0 = d0lo; d0 <= d0hi; d0++)
    for (int d1 = d1lo; d1 <= d1hi; d1++)
    for (int d2 = d2lo; d2 <= d2hi; d2++) {
        int nbin = (d0*NBIN + d1)*NBIN + d2;
        int s = g_binstart[nbin], c = g_bincnt[nbin];
        if (pos + c > SCAP) c = SCAP - pos;
        for (int t = threadIdx.x; t < c; t += 128) {
            int j = g_binpts[s + t];
            float4 col = g_col[j];
            sj[pos + t] = j;
            s0[pos + t] = col.x; s1[pos + t] = col.y; s2[pos + t] = col.z;
        }
        pos += c;
    }
    __syncthreads();

    const int lane = threadIdx.x & 31;
    const int w    = threadIdx.x >> 5;
    const int mybase = g_binstart[b];

    for (int p = w; p < cnt; p += 4) {
        int i = g_binpts[mybase + p];
        float4 ci = g_col[i];
        int iz = i >> 10, iy = (i >> 5) & 31, ix = i & 31;
        int   acc = 0;
        float nb  = 0.f;
        for (int base = 0; base < pos; base += 32) {
            int idx = base + lane;
            float ev = 1e30f; int j = 0;
            if (idx < pos) {
                j = sj[idx];
                float dz = (float)(iz - (j >> 10));
                float dy = (float)(iy - ((j >> 5) & 31));
                float dx = (float)(ix - (j & 31));
                float u3 = ci.x - s0[idx];
                float u4 = ci.y - s1[idx];
                float u5 = ci.z - s2[idx];
                ev = (dz*dz + dy*dy + dx*dx) * (SA*SA) + u3*u3 + u4*u4 + u5*u5;
            }
            bool a = (ev <= ECUT);
            unsigned m = __ballot_sync(0xffffffffu, a);
            if (a) {
                int off = acc + __popc(m & ((1u << lane) - 1u));
                if (off < CAP) {
                    float kv = __expf(-ev);
                    g_nn[i*CAP + off] = make_float2(__int_as_float(j), kv);
                    nb += kv;
                }
            }
            acc += __popc(m);
        }
        for (int o = 16; o; o >>= 1) nb += __shfl_xor_sync(0xffffffffu, nb, o);
        if (acc > CAP) acc = CAP;
        if (lane == 0) { g_ncnt[i] = acc; g_nbi[i] = nb; }
    }
}

// ---------------------------------------------------------------------------
__global__ void k_zb()
{
    if (blockIdx.x < 768) {
        int e = blockIdx.x * 256 + threadIdx.x;
        int i = e / LP, l = e - i*LP;
        int zbase = i & 1023;
        int z = i >> 10;
        float acc = 0.f;
        #pragma unroll
        for (int zp = 0; zp < DD; zp++)
            acc += g_kg[z*32 + zp] * g_qT[((zp << 10) | zbase)*LP + l];
        g_t1[e] = acc;
    } else {
        int w    = ((blockIdx.x - 768) * 256 + threadIdx.x) >> 5;
        int lane = threadIdx.x & 31;
        if (lane >= LP) return;
        int cnt  = g_ncnt[w];
        const float2* pp = &g_nn[w*CAP];
        float acc = 0.f;
        int n = 0;
        for (; n + 4 <= cnt; n += 4) {
            float2 p0 = pp[n],   p1 = pp[n+1], p2 = pp[n+2], p3 = pp[n+3];
            float a0 = g_qT[__float_as_int(p0.x)*LP + lane];
            float a1 = g_qT[__float_as_int(p1.x)*LP + lane];
            float a2 = g_qT[__float_as_int(p2.x)*LP + lane];
            float a3 = g_qT[__float_as_int(p3.x)*LP + lane];
            acc += p0.y*a0; acc += p1.y*a1; acc += p2.y*a2; acc += p3.y*a3;
        }
        for (; n < cnt; n++) { float2 p = pp[n]; acc += p.y * g_qT[__float_as_int(p.x)*LP + lane]; }
        g_bi[w*LP + lane] = acc;
    }
}

// ---------------------------------------------------------------------------
__global__ void k_convy()
{
    __shared__ float sh[32*LP];
    int z = blockIdx.x >> 5, x = blockIdx.x & 31;
    int tid = threadIdx.x;                 // 768
    int y = tid / LP, l = tid - y*LP;
    int i = (z << 10) + (y << 5) + x;
    sh[tid] = g_t1[i*LP + l];
    __syncthreads();
    float acc = 0.f;
    const float* kr = &g_kg[y*32];
    #pragma unroll 8
    for (int yp = 0; yp < 32; yp++) acc += kr[yp] * sh[yp*LP + l];
    g_t2[i*LP + l] = acc;
}

// ---------------------------------------------------------------------------
__global__ void k_final(float* __restrict__ out, int last)
{
    __shared__ float sh[32*LP];
    __shared__ float sc[32*LP];
    __shared__ float wsp[LL*LL], wbi[LL*LL];
    int z = blockIdx.x >> 5, y = blockIdx.x & 31;
    int tid = threadIdx.x;                 // 768
    int x = tid / LP, l = tid - x*LP;
    for (int e = tid; e < LL*LL; e += 768) { wsp[e] = g_CWsp[e]; wbi[e] = g_CWbi[e]; }
    int i = (z << 10) + (y << 5) + x;
    sh[tid] = g_t2[i*LP + l];
    __syncthreads();

    float sp = 0.f;
    {
        const float* kr = &g_kg[x*32];
        #pragma unroll 8
        for (int xp = 0; xp < 32; xp++) sp += kr[xp] * sh[xp*LP + l];
    }
    float nsp = g_sz[z] * g_syx[y] * g_syx[x];
    float nbi = g_nbi[i];
    __syncthreads();
    sh[tid] = sp / nsp;
    sc[tid] = g_bi[i*LP + l] / nbi;
    __syncthreads();

    float cur = -1e30f;
    if (l < LL) {
        float msg = 0.f;
        #pragma unroll
        for (int m = 0; m < LL; m++)
            msg += wsp[l*LL + m] * sh[x*LP + m] + wbi[l*LL + m] * sc[x*LP + m];
        cur = g_uT[i*LP + l] + msg;
    }
    __syncthreads();
    sh[tid] = cur;
    __syncthreads();

    float mx = -1e30f;
    #pragma unroll
    for (int m = 0; m < LL; m++) mx = fmaxf(mx, sh[x*LP + m]);
    float e = __expf(cur - mx);
    __syncthreads();
    sc[tid] = e;
    __syncthreads();
    float se = 0.f;
    #pragma unroll
    for (int m = 0; m < LL; m++) se += sc[x*LP + m];
    float q = e / se;
    g_qT[i*LP + l] = (l < LL) ? q : 0.f;
    if (last && l < LL) out[l*NPIX + i] = q;
}

// ---------------------------------------------------------------------------
extern "C" void kernel_launch(void* const* d_in, const int* in_sizes, int n_in,
                              void* d_out, int out_size)
{
    (void)in_sizes; (void)n_in; (void)out_size;
    const float* image  = (const float*)d_in[0];
    const float* logits = (const float*)d_in[1];
    const float* unary  = (const float*)d_in[2];
    const float* Wsp    = (const float*)d_in[3];
    const float* Wbi    = (const float*)d_in[4];
    const float* C      = (const float*)d_in[5];
    float* out = (float*)d_out;

    void* p_cnt = 0; void* p_cur = 0;
    cudaGetSymbolAddress(&p_cnt, g_bincnt);
    cudaGetSymbolAddress(&p_cur, g_bincur);
    cudaMemsetAsync(p_cnt, 0, NBIN3 * sizeof(int));
    cudaMemsetAsync(p_cur, 0, NBIN3 * sizeof(int));

    k_prep<<<64, 128>>>(image, logits, unary);
    k_scan<<<1, 1024>>>(Wsp, Wbi, C);
    k_scatter<<<64, 128>>>();
    k_sortbins<<<14, 128>>>();
    k_build<<<NBIN3, 128>>>();

    for (int it = 0; it < NITER; it++) {
        k_zb<<<1792, 256>>>();
        k_convy<<<256, 768>>>();
        k_final<<<256, 768>>>(out, it == NITER - 1);
    }
}

// round 9
// speedup vs baseline: 2.4943x; 1.1127x over previous
#include <cuda_runtime.h>
#include <stdint.h>

// ---------------------------------------------------------------------------
// DenseCRF mean-field (R6):
//   * separable spatial Gaussian; z-conv + y-conv fused in one smem pass
//   * color-sparse bilateral kernel (~17 nbrs/pixel), fused into same launch
//   * register-resident per-bin sort (was a 13.7us global-latency chain)
//   * 2 launches per iteration
// ---------------------------------------------------------------------------

#define NPIX   8192
#define DD     8
#define LL     21
#define LP     24
#define NITER  5
#define NBIN   12
#define NBIN3  1728
#define CAP    128
#define SCAP   2048
#define ECUT   23.0f

#define SA (1.0f/(160.0f*1.41421356237f))
#define SB (1.0f/(3.0f*1.41421356237f))

// ------------------------------- scratch -----------------------------------
__device__ float4 g_col[NPIX];
__device__ int    g_binid[NPIX];
__device__ int    g_binstart[NBIN3];
__device__ int    g_bincnt[NBIN3];
__device__ int    g_bincur[NBIN3];
__device__ int    g_binpts[NPIX];
__device__ float2 g_nn[NPIX*CAP];     // (.x = bitcast idx, .y = kernel value)
__device__ int    g_ncnt[NPIX];
__device__ float  g_nbi[NPIX];
__device__ float  g_qT[NPIX*LP];
__device__ float  g_uT[NPIX*LP];      // unary transposed, pixel-major
__device__ float  g_t2[NPIX*LP];      // after z+y conv
__device__ float  g_bi[NPIX*LP];
__device__ float  g_CWsp[LL*LL];
__device__ float  g_CWbi[LL*LL];
__device__ float  g_kg[32*32];
__device__ float  g_sz[8];
__device__ float  g_syx[32];

// ---------------------------------------------------------------------------
__global__ void k_prep(const float* __restrict__ image,
                       const float* __restrict__ logits,
                       const float* __restrict__ unary)
{
    int i = blockIdx.x * blockDim.x + threadIdx.x;    // 8192
    float c0 = image[i], c1 = image[NPIX + i], c2 = image[2*NPIX + i];
    g_col[i] = make_float4(c0*SB, c1*SB, c2*SB, 0.f);
    int b0 = (int)(c0 * (12.0f/255.0f)); b0 = b0 < 0 ? 0 : (b0 > 11 ? 11 : b0);
    int b1 = (int)(c1 * (12.0f/255.0f)); b1 = b1 < 0 ? 0 : (b1 > 11 ? 11 : b1);
    int b2 = (int)(c2 * (12.0f/255.0f)); b2 = b2 < 0 ? 0 : (b2 > 11 ? 11 : b2);
    int bin = (b0*NBIN + b1)*NBIN + b2;
    g_binid[i] = bin;
    atomicAdd(&g_bincnt[bin], 1);

    float v[LL]; float mx = -1e30f;
    #pragma unroll
    for (int l = 0; l < LL; l++) { v[l] = logits[l*NPIX + i]; mx = fmaxf(mx, v[l]); }
    float s = 0.f;
    #pragma unroll
    for (int l = 0; l < LL; l++) { v[l] = __expf(v[l] - mx); s += v[l]; }
    float inv = 1.0f / s;
    #pragma unroll
    for (int l = 0; l < LL; l++) g_qT[i*LP + l] = v[l] * inv;
    g_qT[i*LP + 21] = 0.f; g_qT[i*LP + 22] = 0.f; g_qT[i*LP + 23] = 0.f;

    #pragma unroll
    for (int l = 0; l < LL; l++) g_uT[i*LP + l] = unary[l*NPIX + i];
}

// ---------------------------------------------------------------------------
__global__ void k_scan(const float* __restrict__ Wsp,
                       const float* __restrict__ Wbi,
                       const float* __restrict__ C)
{
    __shared__ int scnt[NBIN3];
    __shared__ int csum[28];
    const int tid = threadIdx.x;                 // 1024

    for (int e = tid; e < LL*LL; e += 1024) {
        int l = e / LL, m = e - l*LL;
        float a = 0.f, b = 0.f;
        for (int k = 0; k < LL; k++) {
            float c = C[l*LL + k];
            a += c * Wsp[k*LL + m];
            b += c * Wbi[k*LL + m];
        }
        g_CWsp[e] = a; g_CWbi[e] = b;
    }
    {
        int a = tid >> 5, b = tid & 31;
        float d = (float)(a - b) * (1.0f/3.0f);
        g_kg[tid] = __expf(-0.5f * d * d);
    }
    if (tid < 32) {
        float s = 0.f;
        for (int b = 0; b < 32; b++) { float d = (float)(tid-b)*(1.0f/3.0f); s += __expf(-0.5f*d*d); }
        g_syx[tid] = s;
    } else if (tid < 40) {
        int a = tid - 32; float s = 0.f;
        for (int b = 0; b < 8; b++) { float d = (float)(a-b)*(1.0f/3.0f); s += __expf(-0.5f*d*d); }
        g_sz[a] = s;
    }
    for (int e = tid; e < NBIN3; e += 1024) scnt[e] = g_bincnt[e];
    __syncthreads();
    if (tid < 27) {
        int s = 0;
        for (int k = 0; k < 64; k++) s += scnt[tid*64 + k];
        csum[tid] = s;
    }
    __syncthreads();
    if (tid == 0) {
        int s = 0;
        for (int c = 0; c < 27; c++) { int t = csum[c]; csum[c] = s; s += t; }
    }
    __syncthreads();
    for (int b = tid; b < NBIN3; b += 1024) {
        int chunk = b >> 6;
        int s = csum[chunk];
        for (int k = chunk*64; k < b; k++) s += scnt[k];
        g_binstart[b] = s;
    }
}

// ---------------------------------------------------------------------------
__global__ void k_scatter()
{
    int i = blockIdx.x * blockDim.x + threadIdx.x;    // 8192
    int b = g_binid[i];
    int off = atomicAdd(&g_bincur[b], 1);
    g_binpts[g_binstart[b] + off] = i;
}

// per-bin ascending sort -> deterministic CSR order.
// Register-resident: independent batched loads, in-register sort, write back.
__global__ void k_sortbins()
{
    int b = blockIdx.x * blockDim.x + threadIdx.x;
    if (b >= NBIN3) return;
    int s = g_binstart[b], c = g_bincnt[b];
    if (c <= 1) return;
    if (c <= 32) {
        int buf[32];
        #pragma unroll 4
        for (int k = 0; k < c; k++) buf[k] = g_binpts[s + k];   // MLP loads
        for (int a = 1; a < c; a++) {
            int v = buf[a]; int k = a - 1;
            while (k >= 0 && buf[k] > v) { buf[k + 1] = buf[k]; k--; }
            buf[k + 1] = v;
        }
        #pragma unroll 4
        for (int k = 0; k < c; k++) g_binpts[s + k] = buf[k];
    } else {            // rare huge bin: in-place fallback
        for (int a = 1; a < c; a++) {
            int v = g_binpts[s + a]; int k = a - 1;
            while (k >= 0 && g_binpts[s + k] > v) { g_binpts[s + k + 1] = g_binpts[s + k]; k--; }
            g_binpts[s + k + 1] = v;
        }
    }
}

// ---------------------------------------------------------------------------
__global__ void k_build()
{
    __shared__ int   sj[SCAP];
    __shared__ float s0[SCAP], s1[SCAP], s2[SCAP];
    const int b   = blockIdx.x;
    const int cnt = g_bincnt[b];
    if (cnt == 0) return;

    int b0 = b / 144, r = b - b0*144, b1 = r / 12, b2 = r - b1*12;
    int d0lo = b0 > 0 ? b0-1 : 0, d0hi = b0 < 11 ? b0+1 : 11;
    int d1lo = b1 > 0 ? b1-1 : 0, d1hi = b1 < 11 ? b1+1 : 11;
    int d2lo = b2 > 0 ? b2-1 : 0, d2hi = b2 < 11 ? b2+1 : 11;

    int pos = 0;
    for (int d0 = d0lo; d0 <= d0hi; d0++)
    for (int d1 = d1lo; d1 <= d1hi; d1++)
    for (int d2 = d2lo; d2 <= d2hi; d2++) {
        int nbin = (d0*NBIN + d1)*NBIN + d2;
        int s = g_binstart[nbin], c = g_bincnt[nbin];
        if (pos + c > SCAP) c = SCAP - pos;
        for (int t = threadIdx.x; t < c; t += 128) {
            int j = g_binpts[s + t];
            float4 col = g_col[j];
            sj[pos + t] = j;
            s0[pos + t] = col.x; s1[pos + t] = col.y; s2[pos + t] = col.z;
        }
        pos += c;
    }
    __syncthreads();

    const int lane = threadIdx.x & 31;
    const int w    = threadIdx.x >> 5;
    const int mybase = g_binstart[b];

    for (int p = w; p < cnt; p += 4) {
        int i = g_binpts[mybase + p];
        float4 ci = g_col[i];
        int iz = i >> 10, iy = (i >> 5) & 31, ix = i & 31;
        int   acc = 0;
        float nb  = 0.f;
        for (int base = 0; base < pos; base += 32) {
            int idx = base + lane;
            float ev = 1e30f; int j = 0;
            if (idx < pos) {
                j = sj[idx];
                float dz = (float)(iz - (j >> 10));
                float dy = (float)(iy - ((j >> 5) & 31));
                float dx = (float)(ix - (j & 31));
                float u3 = ci.x - s0[idx];
                float u4 = ci.y - s1[idx];
                float u5 = ci.z - s2[idx];
                ev = (dz*dz + dy*dy + dx*dx) * (SA*SA) + u3*u3 + u4*u4 + u5*u5;
            }
            bool a = (ev <= ECUT);
            unsigned m = __ballot_sync(0xffffffffu, a);
            if (a) {
                int off = acc + __popc(m & ((1u << lane) - 1u));
                if (off < CAP) {
                    float kv = __expf(-ev);
                    g_nn[i*CAP + off] = make_float2(__int_as_float(j), kv);
                    nb += kv;
                }
            }
            acc += __popc(m);
        }
        for (int o = 16; o; o >>= 1) nb += __shfl_xor_sync(0xffffffffu, nb, o);
        if (acc > CAP) acc = CAP;
        if (lane == 0) { g_ncnt[i] = acc; g_nbi[i] = nb; }
    }
}

// ---------------------------------------------------------------------------
// Iteration part A (one launch):
//   blocks [0,256):    fused z-conv + y-conv for one (z,x) column -> g_t2
//   blocks [256,598):  sparse bilateral gather (24 warps = 24 pixels each)
// Both only read g_qT.
// ---------------------------------------------------------------------------
__global__ void k_iterA()
{
    if (blockIdx.x < 256) {
        __shared__ float t1s[32*LP];
        int z = blockIdx.x >> 5, x = blockIdx.x & 31;
        int tid = threadIdx.x;                 // 768
        int y = tid / LP, l = tid - y*LP;
        int i = (z << 10) + (y << 5) + x;
        float a = 0.f;
        #pragma unroll
        for (int zp = 0; zp < DD; zp++)
            a += g_kg[z*32 + zp] * g_qT[(((zp << 10) | (y << 5) | x))*LP + l];
        t1s[tid] = a;
        __syncthreads();
        float a2 = 0.f;
        const float* kr = &g_kg[y*32];
        #pragma unroll 8
        for (int yp = 0; yp < 32; yp++) a2 += kr[yp] * t1s[yp*LP + l];
        g_t2[i*LP + l] = a2;
    } else {
        int w    = (blockIdx.x - 256) * 24 + (threadIdx.x >> 5);
        int lane = threadIdx.x & 31;
        if (w >= NPIX || lane >= LP) return;
        int cnt  = g_ncnt[w];
        const float2* pp = &g_nn[w*CAP];
        float acc = 0.f;
        int n = 0;
        for (; n + 4 <= cnt; n += 4) {
            float2 p0 = pp[n],   p1 = pp[n+1], p2 = pp[n+2], p3 = pp[n+3];
            float a0 = g_qT[__float_as_int(p0.x)*LP + lane];
            float a1 = g_qT[__float_as_int(p1.x)*LP + lane];
            float a2 = g_qT[__float_as_int(p2.x)*LP + lane];
            float a3 = g_qT[__float_as_int(p3.x)*LP + lane];
            acc += p0.y*a0; acc += p1.y*a1; acc += p2.y*a2; acc += p3.y*a3;
        }
        for (; n < cnt; n++) { float2 p = pp[n]; acc += p.y * g_qT[__float_as_int(p.x)*LP + lane]; }
        g_bi[w*LP + lane] = acc;
    }
}

// ---------------------------------------------------------------------------
// Iteration part B: x-conv + normalize + mixing + unary + softmax.
// ---------------------------------------------------------------------------
__global__ void k_final(float* __restrict__ out, int last)
{
    __shared__ float sh[32*LP];
    __shared__ float sc[32*LP];
    __shared__ float wsp[LL*LL], wbi[LL*LL];
    int z = blockIdx.x >> 5, y = blockIdx.x & 31;
    int tid = threadIdx.x;                 // 768
    int x = tid / LP, l = tid - x*LP;
    for (int e = tid; e < LL*LL; e += 768) { wsp[e] = g_CWsp[e]; wbi[e] = g_CWbi[e]; }
    int i = (z << 10) + (y << 5) + x;
    sh[tid] = g_t2[i*LP + l];
    __syncthreads();

    float sp = 0.f;
    {
        const float* kr = &g_kg[x*32];
        #pragma unroll 8
        for (int xp = 0; xp < 32; xp++) sp += kr[xp] * sh[xp*LP + l];
    }
    float nsp = g_sz[z] * g_syx[y] * g_syx[x];
    float nbi = g_nbi[i];
    __syncthreads();
    sh[tid] = sp / nsp;
    sc[tid] = g_bi[i*LP + l] / nbi;
    __syncthreads();

    float cur = -1e30f;
    if (l < LL) {
        float msg = 0.f;
        #pragma unroll
        for (int m = 0; m < LL; m++)
            msg += wsp[l*LL + m] * sh[x*LP + m] + wbi[l*LL + m] * sc[x*LP + m];
        cur = g_uT[i*LP + l] + msg;
    }
    __syncthreads();
    sh[tid] = cur;
    __syncthreads();

    float mx = -1e30f;
    #pragma unroll
    for (int m = 0; m < LL; m++) mx = fmaxf(mx, sh[x*LP + m]);
    float e = __expf(cur - mx);
    __syncthreads();
    sc[tid] = e;
    __syncthreads();
    float se = 0.f;
    #pragma unroll
    for (int m = 0; m < LL; m++) se += sc[x*LP + m];
    float q = e / se;
    g_qT[i*LP + l] = (l < LL) ? q : 0.f;
    if (last && l < LL) out[l*NPIX + i] = q;
}

// ---------------------------------------------------------------------------
extern "C" void kernel_launch(void* const* d_in, const int* in_sizes, int n_in,
                              void* d_out, int out_size)
{
    (void)in_sizes; (void)n_in; (void)out_size;
    const float* image  = (const float*)d_in[0];
    const float* logits = (const float*)d_in[1];
    const float* unary  = (const float*)d_in[2];
    const float* Wsp    = (const float*)d_in[3];
    const float* Wbi    = (const float*)d_in[4];
    const float* C      = (const float*)d_in[5];
    float* out = (float*)d_out;

    void* p_cnt = 0; void* p_cur = 0;
    cudaGetSymbolAddress(&p_cnt, g_bincnt);
    cudaGetSymbolAddress(&p_cur, g_bincur);
    cudaMemsetAsync(p_cnt, 0, NBIN3 * sizeof(int));
    cudaMemsetAsync(p_cur, 0, NBIN3 * sizeof(int));

    k_prep<<<64, 128>>>(image, logits, unary);
    k_scan<<<1, 1024>>>(Wsp, Wbi, C);
    k_scatter<<<64, 128>>>();
    k_sortbins<<<54, 32>>>();
    k_build<<<NBIN3, 128>>>();

    for (int it = 0; it < NITER; it++) {
        k_iterA<<<598, 768>>>();
        k_final<<<256, 768>>>(out, it == NITER - 1);
    }
}

// round 10
// speedup vs baseline: 2.9447x; 1.1806x over previous
#include <cuda_runtime.h>
#include <stdint.h>

// ---------------------------------------------------------------------------
// DenseCRF mean-field (R7):
//   * separable spatial Gaussian; z-conv + y-conv fused in one smem pass
//   * color-sparse bilateral kernel (~17 nbrs/pixel), fused into same launch
//   * smem-resident per-bin sort (register version spilled to local)
//   * k_build staging parallelized (27-step serial chain -> flat copy)
// ---------------------------------------------------------------------------

#define NPIX   8192
#define DD     8
#define LL     21
#define LP     24
#define NITER  5
#define NBIN   12
#define NBIN3  1728
#define CAP    128
#define SCAP   2048
#define ECUT   23.0f

#define SA (1.0f/(160.0f*1.41421356237f))
#define SB (1.0f/(3.0f*1.41421356237f))

// ------------------------------- scratch -----------------------------------
__device__ float4 g_col[NPIX];
__device__ int    g_binid[NPIX];
__device__ int    g_binstart[NBIN3];
__device__ int    g_bincnt[NBIN3];
__device__ int    g_bincur[NBIN3];
__device__ int    g_binpts[NPIX];
__device__ float2 g_nn[NPIX*CAP];     // (.x = bitcast idx, .y = kernel value)
__device__ int    g_ncnt[NPIX];
__device__ float  g_nbi[NPIX];
__device__ float  g_qT[NPIX*LP];
__device__ float  g_uT[NPIX*LP];      // unary transposed, pixel-major
__device__ float  g_t2[NPIX*LP];      // after z+y conv
__device__ float  g_bi[NPIX*LP];
__device__ float  g_CWsp[LL*LL];
__device__ float  g_CWbi[LL*LL];
__device__ float  g_kg[32*32];
__device__ float  g_sz[8];
__device__ float  g_syx[32];

// ---------------------------------------------------------------------------
__global__ void k_prep(const float* __restrict__ image,
                       const float* __restrict__ logits,
                       const float* __restrict__ unary)
{
    int i = blockIdx.x * blockDim.x + threadIdx.x;    // 8192
    float c0 = image[i], c1 = image[NPIX + i], c2 = image[2*NPIX + i];
    g_col[i] = make_float4(c0*SB, c1*SB, c2*SB, 0.f);
    int b0 = (int)(c0 * (12.0f/255.0f)); b0 = b0 < 0 ? 0 : (b0 > 11 ? 11 : b0);
    int b1 = (int)(c1 * (12.0f/255.0f)); b1 = b1 < 0 ? 0 : (b1 > 11 ? 11 : b1);
    int b2 = (int)(c2 * (12.0f/255.0f)); b2 = b2 < 0 ? 0 : (b2 > 11 ? 11 : b2);
    int bin = (b0*NBIN + b1)*NBIN + b2;
    g_binid[i] = bin;
    atomicAdd(&g_bincnt[bin], 1);

    float v[LL]; float mx = -1e30f;
    #pragma unroll
    for (int l = 0; l < LL; l++) { v[l] = logits[l*NPIX + i]; mx = fmaxf(mx, v[l]); }
    float s = 0.f;
    #pragma unroll
    for (int l = 0; l < LL; l++) { v[l] = __expf(v[l] - mx); s += v[l]; }
    float inv = 1.0f / s;
    #pragma unroll
    for (int l = 0; l < LL; l++) g_qT[i*LP + l] = v[l] * inv;
    g_qT[i*LP + 21] = 0.f; g_qT[i*LP + 22] = 0.f; g_qT[i*LP + 23] = 0.f;

    #pragma unroll
    for (int l = 0; l < LL; l++) g_uT[i*LP + l] = unary[l*NPIX + i];
}

// ---------------------------------------------------------------------------
__global__ void k_scan(const float* __restrict__ Wsp,
                       const float* __restrict__ Wbi,
                       const float* __restrict__ C)
{
    __shared__ int scnt[NBIN3];
    __shared__ int csum[28];
    const int tid = threadIdx.x;                 // 1024

    for (int e = tid; e < LL*LL; e += 1024) {
        int l = e / LL, m = e - l*LL;
        float a = 0.f, b = 0.f;
        for (int k = 0; k < LL; k++) {
            float c = C[l*LL + k];
            a += c * Wsp[k*LL + m];
            b += c * Wbi[k*LL + m];
        }
        g_CWsp[e] = a; g_CWbi[e] = b;
    }
    {
        int a = tid >> 5, b = tid & 31;
        float d = (float)(a - b) * (1.0f/3.0f);
        g_kg[tid] = __expf(-0.5f * d * d);
    }
    if (tid < 32) {
        float s = 0.f;
        for (int b = 0; b < 32; b++) { float d = (float)(tid-b)*(1.0f/3.0f); s += __expf(-0.5f*d*d); }
        g_syx[tid] = s;
    } else if (tid < 40) {
        int a = tid - 32; float s = 0.f;
        for (int b = 0; b < 8; b++) { float d = (float)(a-b)*(1.0f/3.0f); s += __expf(-0.5f*d*d); }
        g_sz[a] = s;
    }
    for (int e = tid; e < NBIN3; e += 1024) scnt[e] = g_bincnt[e];
    __syncthreads();
    if (tid < 27) {
        int s = 0;
        for (int k = 0; k < 64; k++) s += scnt[tid*64 + k];
        csum[tid] = s;
    }
    __syncthreads();
    if (tid == 0) {
        int s = 0;
        for (int c = 0; c < 27; c++) { int t = csum[c]; csum[c] = s; s += t; }
    }
    __syncthreads();
    for (int b = tid; b < NBIN3; b += 1024) {
        int chunk = b >> 6;
        int s = csum[chunk];
        for (int k = chunk*64; k < b; k++) s += scnt[k];
        g_binstart[b] = s;
    }
}

// ---------------------------------------------------------------------------
__global__ void k_scatter()
{
    int i = blockIdx.x * blockDim.x + threadIdx.x;    // 8192
    int b = g_binid[i];
    int off = atomicAdd(&g_bincur[b], 1);
    g_binpts[g_binstart[b] + off] = i;
}

// per-bin ascending sort -> deterministic CSR order. Smem-resident buffers
// (a dynamically indexed thread-local array spills to local memory).
__global__ void k_sortbins()
{
    __shared__ int sbuf[128 * 32];
    int t = threadIdx.x;                               // 128 threads
    int b = blockIdx.x * 128 + t;
    if (b >= NBIN3) return;
    int s = g_binstart[b], c = g_bincnt[b];
    if (c <= 1) return;
    int* buf = &sbuf[t * 32];
    if (c <= 32) {
        for (int k = 0; k < c; k++) buf[k] = g_binpts[s + k];   // independent loads
        for (int a = 1; a < c; a++) {
            int v = buf[a]; int k = a - 1;
            while (k >= 0 && buf[k] > v) { buf[k + 1] = buf[k]; k--; }
            buf[k + 1] = v;
        }
        for (int k = 0; k < c; k++) g_binpts[s + k] = buf[k];
    } else {            // rare huge bin: in-place fallback
        for (int a = 1; a < c; a++) {
            int v = g_binpts[s + a]; int k = a - 1;
            while (k >= 0 && g_binpts[s + k] > v) { g_binpts[s + k + 1] = g_binpts[s + k]; k--; }
            g_binpts[s + k + 1] = v;
        }
    }
}

// ---------------------------------------------------------------------------
// Build sparse bilateral rows per bin. Candidate staging fully parallel:
// metadata for <=27 neighbor bins fetched at once, flat cooperative copy.
// ---------------------------------------------------------------------------
__global__ void k_build()
{
    __shared__ int   sj[SCAP];
    __shared__ float s0[SCAP], s1[SCAP], s2[SCAP];
    __shared__ int   nstart[27], npre[28];
    const int tid = threadIdx.x;                       // 128
    const int b   = blockIdx.x;
    const int cnt = g_bincnt[b];
    if (cnt == 0) return;

    int b0 = b / 144, r = b - b0*144, b1 = r / 12, b2 = r - b1*12;
    int d0lo = b0 > 0 ? b0-1 : 0, d0hi = b0 < 11 ? b0+1 : 11;
    int d1lo = b1 > 0 ? b1-1 : 0, d1hi = b1 < 11 ? b1+1 : 11;
    int d2lo = b2 > 0 ? b2-1 : 0, d2hi = b2 < 11 ? b2+1 : 11;
    int n0 = d0hi-d0lo+1, n1 = d1hi-d1lo+1, n2 = d2hi-d2lo+1;
    int nseg = n0*n1*n2;                               // <= 27

    // parallel metadata fetch (lex order over (d0,d1,d2) = previous order)
    if (tid < nseg) {
        int q = tid;
        int e0 = q / (n1*n2); q -= e0*(n1*n2);
        int e1 = q / n2, e2 = q - e1*n2;
        int nbin = ((d0lo+e0)*NBIN + (d1lo+e1))*NBIN + (d2lo+e2);
        nstart[tid] = g_binstart[nbin];
        npre[tid]   = g_bincnt[nbin];
    }
    __syncthreads();
    if (tid == 0) {
        int s = 0;
        for (int k = 0; k < nseg; k++) { int c = npre[k]; npre[k] = s; s += c; }
        npre[nseg] = s;
    }
    __syncthreads();
    int tot = npre[nseg]; if (tot > SCAP) tot = SCAP;

    // flat cooperative copy of all candidates
    for (int idx = tid; idx < tot; idx += 128) {
        int seg = 0;
        while (seg + 1 < nseg && npre[seg + 1] <= idx) seg++;
        int j = g_binpts[nstart[seg] + (idx - npre[seg])];
        float4 col = g_col[j];
        sj[idx] = j;
        s0[idx] = col.x; s1[idx] = col.y; s2[idx] = col.z;
    }
    __syncthreads();

    const int lane = tid & 31;
    const int w    = tid >> 5;
    const int mybase = g_binstart[b];
    const int pos = tot;

    for (int p = w; p < cnt; p += 4) {
        int i = g_binpts[mybase + p];
        float4 ci = g_col[i];
        int iz = i >> 10, iy = (i >> 5) & 31, ix = i & 31;
        int   acc = 0;
        float nb  = 0.f;
        for (int base = 0; base < pos; base += 32) {
            int idx = base + lane;
            float ev = 1e30f; int j = 0;
            if (idx < pos) {
                j = sj[idx];
                float dz = (float)(iz - (j >> 10));
                float dy = (float)(iy - ((j >> 5) & 31));
                float dx = (float)(ix - (j & 31));
                float u3 = ci.x - s0[idx];
                float u4 = ci.y - s1[idx];
                float u5 = ci.z - s2[idx];
                ev = (dz*dz + dy*dy + dx*dx) * (SA*SA) + u3*u3 + u4*u4 + u5*u5;
            }
            bool a = (ev <= ECUT);
            unsigned m = __ballot_sync(0xffffffffu, a);
            if (a) {
                int off = acc + __popc(m & ((1u << lane) - 1u));
                if (off < CAP) {
                    float kv = __expf(-ev);
                    g_nn[i*CAP + off] = make_float2(__int_as_float(j), kv);
                    nb += kv;
                }
            }
            acc += __popc(m);
        }
        for (int o = 16; o; o >>= 1) nb += __shfl_xor_sync(0xffffffffu, nb, o);
        if (acc > CAP) acc = CAP;
        if (lane == 0) { g_ncnt[i] = acc; g_nbi[i] = nb; }
    }
}

// ---------------------------------------------------------------------------
// Iteration part A (one launch):
//   blocks [0,256):    fused z-conv + y-conv for one (z,x) column -> g_t2
//   blocks [256,598):  sparse bilateral gather (24 warps = 24 pixels each)
// ---------------------------------------------------------------------------
__global__ void k_iterA()
{
    if (blockIdx.x < 256) {
        __shared__ float t1s[32*LP];
        int z = blockIdx.x >> 5, x = blockIdx.x & 31;
        int tid = threadIdx.x;                 // 768
        int y = tid / LP, l = tid - y*LP;
        int i = (z << 10) + (y << 5) + x;
        float a = 0.f;
        #pragma unroll
        for (int zp = 0; zp < DD; zp++)
            a += g_kg[z*32 + zp] * g_qT[(((zp << 10) | (y << 5) | x))*LP + l];
        t1s[tid] = a;
        __syncthreads();
        float a2 = 0.f;
        const float* kr = &g_kg[y*32];
        #pragma unroll 8
        for (int yp = 0; yp < 32; yp++) a2 += kr[yp] * t1s[yp*LP + l];
        g_t2[i*LP + l] = a2;
    } else {
        int w    = (blockIdx.x - 256) * 24 + (threadIdx.x >> 5);
        int lane = threadIdx.x & 31;
        if (w >= NPIX || lane >= LP) return;
        int cnt  = g_ncnt[w];
        const float2* pp = &g_nn[w*CAP];
        float acc = 0.f;
        int n = 0;
        for (; n + 4 <= cnt; n += 4) {
            float2 p0 = pp[n],   p1 = pp[n+1], p2 = pp[n+2], p3 = pp[n+3];
            float a0 = g_qT[__float_as_int(p0.x)*LP + lane];
            float a1 = g_qT[__float_as_int(p1.x)*LP + lane];
            float a2 = g_qT[__float_as_int(p2.x)*LP + lane];
            float a3 = g_qT[__float_as_int(p3.x)*LP + lane];
            acc += p0.y*a0; acc += p1.y*a1; acc += p2.y*a2; acc += p3.y*a3;
        }
        for (; n < cnt; n++) { float2 p = pp[n]; acc += p.y * g_qT[__float_as_int(p.x)*LP + lane]; }
        g_bi[w*LP + lane] = acc;
    }
}

// ---------------------------------------------------------------------------
__global__ void k_final(float* __restrict__ out, int last)
{
    __shared__ float sh[32*LP];
    __shared__ float sc[32*LP];
    __shared__ float wsp[LL*LL], wbi[LL*LL];
    int z = blockIdx.x >> 5, y = blockIdx.x & 31;
    int tid = threadIdx.x;                 // 768
    int x = tid / LP, l = tid - x*LP;
    for (int e = tid; e < LL*LL; e += 768) { wsp[e] = g_CWsp[e]; wbi[e] = g_CWbi[e]; }
    int i = (z << 10) + (y << 5) + x;
    sh[tid] = g_t2[i*LP + l];
    __syncthreads();

    float sp = 0.f;
    {
        const float* kr = &g_kg[x*32];
        #pragma unroll 8
        for (int xp = 0; xp < 32; xp++) sp += kr[xp] * sh[xp*LP + l];
    }
    float nsp = g_sz[z] * g_syx[y] * g_syx[x];
    float nbi = g_nbi[i];
    __syncthreads();
    sh[tid] = sp / nsp;
    sc[tid] = g_bi[i*LP + l] / nbi;
    __syncthreads();

    float cur = -1e30f;
    if (l < LL) {
        float msg = 0.f;
        #pragma unroll
        for (int m = 0; m < LL; m++)
            msg += wsp[l*LL + m] * sh[x*LP + m] + wbi[l*LL + m] * sc[x*LP + m];
        cur = g_uT[i*LP + l] + msg;
    }
    __syncthreads();
    sh[tid] = cur;
    __syncthreads();

    float mx = -1e30f;
    #pragma unroll
    for (int m = 0; m < LL; m++) mx = fmaxf(mx, sh[x*LP + m]);
    float e = __expf(cur - mx);
    __syncthreads();
    sc[tid] = e;
    __syncthreads();
    float se = 0.f;
    #pragma unroll
    for (int m = 0; m < LL; m++) se += sc[x*LP + m];
    float q = e / se;
    g_qT[i*LP + l] = (l < LL) ? q : 0.f;
    if (last && l < LL) out[l*NPIX + i] = q;
}

// ---------------------------------------------------------------------------
extern "C" void kernel_launch(void* const* d_in, const int* in_sizes, int n_in,
                              void* d_out, int out_size)
{
    (void)in_sizes; (void)n_in; (void)out_size;
    const float* image  = (const float*)d_in[0];
    const float* logits = (const float*)d_in[1];
    const float* unary  = (const float*)d_in[2];
    const float* Wsp    = (const float*)d_in[3];
    const float* Wbi    = (const float*)d_in[4];
    const float* C      = (const float*)d_in[5];
    float* out = (float*)d_out;

    void* p_cnt = 0; void* p_cur = 0;
    cudaGetSymbolAddress(&p_cnt, g_bincnt);
    cudaGetSymbolAddress(&p_cur, g_bincur);
    cudaMemsetAsync(p_cnt, 0, NBIN3 * sizeof(int));
    cudaMemsetAsync(p_cur, 0, NBIN3 * sizeof(int));

    k_prep<<<64, 128>>>(image, logits, unary);
    k_scan<<<1, 1024>>>(Wsp, Wbi, C);
    k_scatter<<<64, 128>>>();
    k_sortbins<<<14, 128>>>();
    k_build<<<NBIN3, 128>>>();

    for (int it = 0; it < NITER; it++) {
        k_iterA<<<598, 768>>>();
        k_final<<<256, 768>>>(out, it == NITER - 1);
    }
}

// round 11
// speedup vs baseline: 3.0525x; 1.0366x over previous
#include <cuda_runtime.h>
#include <stdint.h>

// ---------------------------------------------------------------------------
// DenseCRF mean-field (R8):
//   * separable spatial Gaussian; z-conv + y-conv fused in one smem pass
//   * color-sparse bilateral kernel (~17 nbrs/pixel), fused into same launch
//   * warp-parallel per-bin rank sort (smem/reg versions were latency chains)
//   * LUT/CW computation overlapped into k_prep; k_scan = prefix only
// ---------------------------------------------------------------------------

#define NPIX   8192
#define DD     8
#define LL     21
#define LP     24
#define NITER  5
#define NBIN   12
#define NBIN3  1728
#define CAP    128
#define SCAP   2048
#define ECUT   23.0f

#define SA (1.0f/(160.0f*1.41421356237f))
#define SB (1.0f/(3.0f*1.41421356237f))

// ------------------------------- scratch -----------------------------------
__device__ float4 g_col[NPIX];
__device__ int    g_binid[NPIX];
__device__ int    g_binstart[NBIN3];
__device__ int    g_bincnt[NBIN3];
__device__ int    g_bincur[NBIN3];
__device__ int    g_binpts[NPIX];
__device__ float2 g_nn[NPIX*CAP];     // (.x = bitcast idx, .y = kernel value)
__device__ int    g_ncnt[NPIX];
__device__ float  g_nbi[NPIX];
__device__ float  g_qT[NPIX*LP];
__device__ float  g_uT[NPIX*LP];      // unary transposed, pixel-major
__device__ float  g_t2[NPIX*LP];      // after z+y conv
__device__ float  g_bi[NPIX*LP];
__device__ float  g_CWsp[LL*LL];
__device__ float  g_CWbi[LL*LL];
__device__ float  g_kg[32*32];
__device__ float  g_sz[8];
__device__ float  g_syx[32];

// ---------------------------------------------------------------------------
// k_prep: blocks [0,64) per-pixel work; block 64 = CW matrices + LUTs.
// ---------------------------------------------------------------------------
__global__ void k_prep(const float* __restrict__ image,
                       const float* __restrict__ logits,
                       const float* __restrict__ unary,
                       const float* __restrict__ Wsp,
                       const float* __restrict__ Wbi,
                       const float* __restrict__ C)
{
    if (blockIdx.x == 64) {
        int tid = threadIdx.x;                 // 128
        for (int e = tid; e < LL*LL; e += 128) {
            int l = e / LL, m = e - l*LL;
            float a = 0.f, b = 0.f;
            for (int k = 0; k < LL; k++) {
                float c = C[l*LL + k];
                a += c * Wsp[k*LL + m];
                b += c * Wbi[k*LL + m];
            }
            g_CWsp[e] = a; g_CWbi[e] = b;
        }
        for (int e = tid; e < 1024; e += 128) {
            int a = e >> 5, b = e & 31;
            float d = (float)(a - b) * (1.0f/3.0f);
            g_kg[e] = __expf(-0.5f * d * d);
        }
        if (tid < 32) {
            float s = 0.f;
            for (int b = 0; b < 32; b++) { float d = (float)(tid-b)*(1.0f/3.0f); s += __expf(-0.5f*d*d); }
            g_syx[tid] = s;
        } else if (tid < 40) {
            int a = tid - 32; float s = 0.f;
            for (int b = 0; b < 8; b++) { float d = (float)(a-b)*(1.0f/3.0f); s += __expf(-0.5f*d*d); }
            g_sz[a] = s;
        }
        return;
    }

    int i = blockIdx.x * blockDim.x + threadIdx.x;    // 8192
    float c0 = image[i], c1 = image[NPIX + i], c2 = image[2*NPIX + i];
    g_col[i] = make_float4(c0*SB, c1*SB, c2*SB, 0.f);
    int b0 = (int)(c0 * (12.0f/255.0f)); b0 = b0 < 0 ? 0 : (b0 > 11 ? 11 : b0);
    int b1 = (int)(c1 * (12.0f/255.0f)); b1 = b1 < 0 ? 0 : (b1 > 11 ? 11 : b1);
    int b2 = (int)(c2 * (12.0f/255.0f)); b2 = b2 < 0 ? 0 : (b2 > 11 ? 11 : b2);
    int bin = (b0*NBIN + b1)*NBIN + b2;
    g_binid[i] = bin;
    atomicAdd(&g_bincnt[bin], 1);

    float v[LL]; float mx = -1e30f;
    #pragma unroll
    for (int l = 0; l < LL; l++) { v[l] = logits[l*NPIX + i]; mx = fmaxf(mx, v[l]); }
    float s = 0.f;
    #pragma unroll
    for (int l = 0; l < LL; l++) { v[l] = __expf(v[l] - mx); s += v[l]; }
    float inv = 1.0f / s;
    #pragma unroll
    for (int l = 0; l < LL; l++) g_qT[i*LP + l] = v[l] * inv;
    g_qT[i*LP + 21] = 0.f; g_qT[i*LP + 22] = 0.f; g_qT[i*LP + 23] = 0.f;

    #pragma unroll
    for (int l = 0; l < LL; l++) g_uT[i*LP + l] = unary[l*NPIX + i];
}

// ---------------------------------------------------------------------------
// k_scan: prefix sum over 1728 bin counts (single block).
// ---------------------------------------------------------------------------
__global__ void k_scan()
{
    __shared__ int scnt[NBIN3];
    __shared__ int csum[28];
    const int tid = threadIdx.x;                 // 1024
    for (int e = tid; e < NBIN3; e += 1024) scnt[e] = g_bincnt[e];
    __syncthreads();
    if (tid < 27) {
        int s = 0;
        for (int k = 0; k < 64; k++) s += scnt[tid*64 + k];
        csum[tid] = s;
    }
    __syncthreads();
    if (tid == 0) {
        int s = 0;
        for (int c = 0; c < 27; c++) { int t = csum[c]; csum[c] = s; s += t; }
    }
    __syncthreads();
    for (int b = tid; b < NBIN3; b += 1024) {
        int chunk = b >> 6;
        int s = csum[chunk];
        for (int k = chunk*64; k < b; k++) s += scnt[k];
        g_binstart[b] = s;
    }
}

// ---------------------------------------------------------------------------
__global__ void k_scatter()
{
    int i = blockIdx.x * blockDim.x + threadIdx.x;    // 8192
    int b = g_binid[i];
    int off = atomicAdd(&g_bincur[b], 1);
    g_binpts[g_binstart[b] + off] = i;
}

// Warp-parallel per-bin rank sort -> deterministic ascending CSR order.
// One warp per bin: coalesced load, 32-shuffle rank, coalesced store.
__global__ void k_sortbins()
{
    int warp = (blockIdx.x * blockDim.x + threadIdx.x) >> 5;   // bin
    int lane = threadIdx.x & 31;
    if (warp >= NBIN3) return;
    int s = g_bincnt[warp] ? g_binstart[warp] : 0;
    int c = g_bincnt[warp];
    if (c <= 1) return;
    if (c <= 32) {
        int v = (lane < c) ? g_binpts[s + lane] : 0x7fffffff;
        int rank = 0;
        #pragma unroll
        for (int o = 0; o < 32; o++) {
            int u = __shfl_sync(0xffffffffu, v, o);
            rank += (u < v) || (u == v && o < lane);
        }
        if (lane < c) g_binpts[s + rank] = v;
    } else if (lane == 0) {       // rare huge bin: serial fallback
        for (int a = 1; a < c; a++) {
            int v = g_binpts[s + a]; int k = a - 1;
            while (k >= 0 && g_binpts[s + k] > v) { g_binpts[s + k + 1] = g_binpts[s + k]; k--; }
            g_binpts[s + k + 1] = v;
        }
    }
}

// ---------------------------------------------------------------------------
// Build sparse bilateral rows per bin. Candidate staging fully parallel.
// ---------------------------------------------------------------------------
__global__ void k_build()
{
    __shared__ int   sj[SCAP];
    __shared__ float s0[SCAP], s1[SCAP], s2[SCAP];
    __shared__ int   nstart[27], npre[28];
    const int tid = threadIdx.x;                       // 128
    const int b   = blockIdx.x;
    const int cnt = g_bincnt[b];
    if (cnt == 0) return;

    int b0 = b / 144, r = b - b0*144, b1 = r / 12, b2 = r - b1*12;
    int d0lo = b0 > 0 ? b0-1 : 0, d0hi = b0 < 11 ? b0+1 : 11;
    int d1lo = b1 > 0 ? b1-1 : 0, d1hi = b1 < 11 ? b1+1 : 11;
    int d2lo = b2 > 0 ? b2-1 : 0, d2hi = b2 < 11 ? b2+1 : 11;
    int n0 = d0hi-d0lo+1, n1 = d1hi-d1lo+1, n2 = d2hi-d2lo+1;
    int nseg = n0*n1*n2;                               // <= 27

    if (tid < nseg) {
        int q = tid;
        int e0 = q / (n1*n2); q -= e0*(n1*n2);
        int e1 = q / n2, e2 = q - e1*n2;
        int nbin = ((d0lo+e0)*NBIN + (d1lo+e1))*NBIN + (d2lo+e2);
        nstart[tid] = g_binstart[nbin];
        npre[tid]   = g_bincnt[nbin];
    }
    __syncthreads();
    if (tid == 0) {
        int s = 0;
        for (int k = 0; k < nseg; k++) { int c = npre[k]; npre[k] = s; s += c; }
        npre[nseg] = s;
    }
    __syncthreads();
    int tot = npre[nseg]; if (tot > SCAP) tot = SCAP;

    for (int idx = tid; idx < tot; idx += 128) {
        int seg = 0;
        while (seg + 1 < nseg && npre[seg + 1] <= idx) seg++;
        int j = g_binpts[nstart[seg] + (idx - npre[seg])];
        float4 col = g_col[j];
        sj[idx] = j;
        s0[idx] = col.x; s1[idx] = col.y; s2[idx] = col.z;
    }
    __syncthreads();

    const int lane = tid & 31;
    const int w    = tid >> 5;
    const int mybase = g_binstart[b];
    const int pos = tot;

    for (int p = w; p < cnt; p += 4) {
        int i = g_binpts[mybase + p];
        float4 ci = g_col[i];
        int iz = i >> 10, iy = (i >> 5) & 31, ix = i & 31;
        int   acc = 0;
        float nb  = 0.f;
        for (int base = 0; base < pos; base += 32) {
            int idx = base + lane;
            float ev = 1e30f; int j = 0;
            if (idx < pos) {
                j = sj[idx];
                float dz = (float)(iz - (j >> 10));
                float dy = (float)(iy - ((j >> 5) & 31));
                float dx = (float)(ix - (j & 31));
                float u3 = ci.x - s0[idx];
                float u4 = ci.y - s1[idx];
                float u5 = ci.z - s2[idx];
                ev = (dz*dz + dy*dy + dx*dx) * (SA*SA) + u3*u3 + u4*u4 + u5*u5;
            }
            bool a = (ev <= ECUT);
            unsigned m = __ballot_sync(0xffffffffu, a);
            if (a) {
                int off = acc + __popc(m & ((1u << lane) - 1u));
                if (off < CAP) {
                    float kv = __expf(-ev);
                    g_nn[i*CAP + off] = make_float2(__int_as_float(j), kv);
                    nb += kv;
                }
            }
            acc += __popc(m);
        }
        for (int o = 16; o; o >>= 1) nb += __shfl_xor_sync(0xffffffffu, nb, o);
        if (acc > CAP) acc = CAP;
        if (lane == 0) { g_ncnt[i] = acc; g_nbi[i] = nb; }
    }
}

// ---------------------------------------------------------------------------
// Iteration part A (one launch):
//   blocks [0,256):    fused z-conv + y-conv for one (z,x) column -> g_t2
//   blocks [256,598):  sparse bilateral gather (24 warps = 24 pixels each)
// ---------------------------------------------------------------------------
__global__ void k_iterA()
{
    if (blockIdx.x < 256) {
        __shared__ float t1s[32*LP];
        int z = blockIdx.x >> 5, x = blockIdx.x & 31;
        int tid = threadIdx.x;                 // 768
        int y = tid / LP, l = tid - y*LP;
        int i = (z << 10) + (y << 5) + x;
        float a = 0.f;
        #pragma unroll
        for (int zp = 0; zp < DD; zp++)
            a += g_kg[z*32 + zp] * g_qT[(((zp << 10) | (y << 5) | x))*LP + l];
        t1s[tid] = a;
        __syncthreads();
        float a2 = 0.f;
        const float* kr = &g_kg[y*32];
        #pragma unroll 8
        for (int yp = 0; yp < 32; yp++) a2 += kr[yp] * t1s[yp*LP + l];
        g_t2[i*LP + l] = a2;
    } else {
        int w    = (blockIdx.x - 256) * 24 + (threadIdx.x >> 5);
        int lane = threadIdx.x & 31;
        if (w >= NPIX || lane >= LP) return;
        int cnt  = g_ncnt[w];
        const float2* pp = &g_nn[w*CAP];
        float acc = 0.f;
        int n = 0;
        for (; n + 4 <= cnt; n += 4) {
            float2 p0 = pp[n],   p1 = pp[n+1], p2 = pp[n+2], p3 = pp[n+3];
            float a0 = g_qT[__float_as_int(p0.x)*LP + lane];
            float a1 = g_qT[__float_as_int(p1.x)*LP + lane];
            float a2 = g_qT[__float_as_int(p2.x)*LP + lane];
            float a3 = g_qT[__float_as_int(p3.x)*LP + lane];
            acc += p0.y*a0; acc += p1.y*a1; acc += p2.y*a2; acc += p3.y*a3;
        }
        for (; n < cnt; n++) { float2 p = pp[n]; acc += p.y * g_qT[__float_as_int(p.x)*LP + lane]; }
        g_bi[w*LP + lane] = acc;
    }
}

// ---------------------------------------------------------------------------
__global__ void k_final(float* __restrict__ out, int last)
{
    __shared__ float sh[32*LP];
    __shared__ float sc[32*LP];
    __shared__ float wsp[LL*LL], wbi[LL*LL];
    int z = blockIdx.x >> 5, y = blockIdx.x & 31;
    int tid = threadIdx.x;                 // 768
    int x = tid / LP, l = tid - x*LP;
    for (int e = tid; e < LL*LL; e += 768) { wsp[e] = g_CWsp[e]; wbi[e] = g_CWbi[e]; }
    int i = (z << 10) + (y << 5) + x;
    sh[tid] = g_t2[i*LP + l];
    __syncthreads();

    float sp = 0.f;
    {
        const float* kr = &g_kg[x*32];
        #pragma unroll 8
        for (int xp = 0; xp < 32; xp++) sp += kr[xp] * sh[xp*LP + l];
    }
    float nsp = g_sz[z] * g_syx[y] * g_syx[x];
    float nbi = g_nbi[i];
    __syncthreads();
    sh[tid] = sp / nsp;
    sc[tid] = g_bi[i*LP + l] / nbi;
    __syncthreads();

    float cur = -1e30f;
    if (l < LL) {
        float msg = 0.f;
        #pragma unroll
        for (int m = 0; m < LL; m++)
            msg += wsp[l*LL + m] * sh[x*LP + m] + wbi[l*LL + m] * sc[x*LP + m];
        cur = g_uT[i*LP + l] + msg;
    }
    __syncthreads();
    sh[tid] = cur;
    __syncthreads();

    float mx = -1e30f;
    #pragma unroll
    for (int m = 0; m < LL; m++) mx = fmaxf(mx, sh[x*LP + m]);
    float e = __expf(cur - mx);
    __syncthreads();
    sc[tid] = e;
    __syncthreads();
    float se = 0.f;
    #pragma unroll
    for (int m = 0; m < LL; m++) se += sc[x*LP + m];
    float q = e / se;
    g_qT[i*LP + l] = (l < LL) ? q : 0.f;
    if (last && l < LL) out[l*NPIX + i] = q;
}

// ---------------------------------------------------------------------------
extern "C" void kernel_launch(void* const* d_in, const int* in_sizes, int n_in,
                              void* d_out, int out_size)
{
    (void)in_sizes; (void)n_in; (void)out_size;
    const float* image  = (const float*)d_in[0];
    const float* logits = (const float*)d_in[1];
    const float* unary  = (const float*)d_in[2];
    const float* Wsp    = (const float*)d_in[3];
    const float* Wbi    = (const float*)d_in[4];
    const float* C      = (const float*)d_in[5];
    float* out = (float*)d_out;

    void* p_cnt = 0; void* p_cur = 0;
    cudaGetSymbolAddress(&p_cnt, g_bincnt);
    cudaGetSymbolAddress(&p_cur, g_bincur);
    cudaMemsetAsync(p_cnt, 0, NBIN3 * sizeof(int));
    cudaMemsetAsync(p_cur, 0, NBIN3 * sizeof(int));

    k_prep<<<65, 128>>>(image, logits, unary, Wsp, Wbi, C);
    k_scan<<<1, 1024>>>();
    k_scatter<<<64, 128>>>();
    k_sortbins<<<54, 1024>>>();
    k_build<<<NBIN3, 128>>>();

    for (int it = 0; it < NITER; it++) {
        k_iterA<<<598, 768>>>();
        k_final<<<256, 768>>>(out, it == NITER - 1);
    }
}

// round 12
// speedup vs baseline: 3.0533x; 1.0003x over previous
#include <cuda_runtime.h>
#include <stdint.h>

// ---------------------------------------------------------------------------
// DenseCRF mean-field (R8):
//   * separable spatial Gaussian; z-conv + y-conv fused in one smem pass
//   * color-sparse bilateral kernel (~17 nbrs/pixel), fused into same launch
//   * warp-parallel per-bin rank sort (smem/reg versions were latency chains)
//   * LUT/CW computation overlapped into k_prep; k_scan = prefix only
// ---------------------------------------------------------------------------

#define NPIX   8192
#define DD     8
#define LL     21
#define LP     24
#define NITER  5
#define NBIN   12
#define NBIN3  1728
#define CAP    128
#define SCAP   2048
#define ECUT   23.0f

#define SA (1.0f/(160.0f*1.41421356237f))
#define SB (1.0f/(3.0f*1.41421356237f))

// ------------------------------- scratch -----------------------------------
__device__ float4 g_col[NPIX];
__device__ int    g_binid[NPIX];
__device__ int    g_binstart[NBIN3];
__device__ int    g_bincnt[NBIN3];
__device__ int    g_bincur[NBIN3];
__device__ int    g_binpts[NPIX];
__device__ float2 g_nn[NPIX*CAP];     // (.x = bitcast idx, .y = kernel value)
__device__ int    g_ncnt[NPIX];
__device__ float  g_nbi[NPIX];
__device__ float  g_qT[NPIX*LP];
__device__ float  g_uT[NPIX*LP];      // unary transposed, pixel-major
__device__ float  g_t2[NPIX*LP];      // after z+y conv
__device__ float  g_bi[NPIX*LP];
__device__ float  g_CWsp[LL*LL];
__device__ float  g_CWbi[LL*LL];
__device__ float  g_kg[32*32];
__device__ float  g_sz[8];
__device__ float  g_syx[32];

// ---------------------------------------------------------------------------
// k_prep: blocks [0,64) per-pixel work; block 64 = CW matrices + LUTs.
// ---------------------------------------------------------------------------
__global__ void k_prep(const float* __restrict__ image,
                       const float* __restrict__ logits,
                       const float* __restrict__ unary,
                       const float* __restrict__ Wsp,
                       const float* __restrict__ Wbi,
                       const float* __restrict__ C)
{
    if (blockIdx.x == 64) {
        int tid = threadIdx.x;                 // 128
        for (int e = tid; e < LL*LL; e += 128) {
            int l = e / LL, m = e - l*LL;
            float a = 0.f, b = 0.f;
            for (int k = 0; k < LL; k++) {
                float c = C[l*LL + k];
                a += c * Wsp[k*LL + m];
                b += c * Wbi[k*LL + m];
            }
            g_CWsp[e] = a; g_CWbi[e] = b;
        }
        for (int e = tid; e < 1024; e += 128) {
            int a = e >> 5, b = e & 31;
            float d = (float)(a - b) * (1.0f/3.0f);
            g_kg[e] = __expf(-0.5f * d * d);
        }
        if (tid < 32) {
            float s = 0.f;
            for (int b = 0; b < 32; b++) { float d = (float)(tid-b)*(1.0f/3.0f); s += __expf(-0.5f*d*d); }
            g_syx[tid] = s;
        } else if (tid < 40) {
            int a = tid - 32; float s = 0.f;
            for (int b = 0; b < 8; b++) { float d = (float)(a-b)*(1.0f/3.0f); s += __expf(-0.5f*d*d); }
            g_sz[a] = s;
        }
        return;
    }

    int i = blockIdx.x * blockDim.x + threadIdx.x;    // 8192
    float c0 = image[i], c1 = image[NPIX + i], c2 = image[2*NPIX + i];
    g_col[i] = make_float4(c0*SB, c1*SB, c2*SB, 0.f);
    int b0 = (int)(c0 * (12.0f/255.0f)); b0 = b0 < 0 ? 0 : (b0 > 11 ? 11 : b0);
    int b1 = (int)(c1 * (12.0f/255.0f)); b1 = b1 < 0 ? 0 : (b1 > 11 ? 11 : b1);
    int b2 = (int)(c2 * (12.0f/255.0f)); b2 = b2 < 0 ? 0 : (b2 > 11 ? 11 : b2);
    int bin = (b0*NBIN + b1)*NBIN + b2;
    g_binid[i] = bin;
    atomicAdd(&g_bincnt[bin], 1);

    float v[LL]; float mx = -1e30f;
    #pragma unroll
    for (int l = 0; l < LL; l++) { v[l] = logits[l*NPIX + i]; mx = fmaxf(mx, v[l]); }
    float s = 0.f;
    #pragma unroll
    for (int l = 0; l < LL; l++) { v[l] = __expf(v[l] - mx); s += v[l]; }
    float inv = 1.0f / s;
    #pragma unroll
    for (int l = 0; l < LL; l++) g_qT[i*LP + l] = v[l] * inv;
    g_qT[i*LP + 21] = 0.f; g_qT[i*LP + 22] = 0.f; g_qT[i*LP + 23] = 0.f;

    #pragma unroll
    for (int l = 0; l < LL; l++) g_uT[i*LP + l] = unary[l*NPIX + i];
}

// ---------------------------------------------------------------------------
// k_scan: prefix sum over 1728 bin counts (single block).
// ---------------------------------------------------------------------------
__global__ void k_scan()
{
    __shared__ int scnt[NBIN3];
    __shared__ int csum[28];
    const int tid = threadIdx.x;                 // 1024
    for (int e = tid; e < NBIN3; e += 1024) scnt[e] = g_bincnt[e];
    __syncthreads();
    if (tid < 27) {
        int s = 0;
        for (int k = 0; k < 64; k++) s += scnt[tid*64 + k];
        csum[tid] = s;
    }
    __syncthreads();
    if (tid == 0) {
        int s = 0;
        for (int c = 0; c < 27; c++) { int t = csum[c]; csum[c] = s; s += t; }
    }
    __syncthreads();
    for (int b = tid; b < NBIN3; b += 1024) {
        int chunk = b >> 6;
        int s = csum[chunk];
        for (int k = chunk*64; k < b; k++) s += scnt[k];
        g_binstart[b] = s;
    }
}

// ---------------------------------------------------------------------------
__global__ void k_scatter()
{
    int i = blockIdx.x * blockDim.x + threadIdx.x;    // 8192
    int b = g_binid[i];
    int off = atomicAdd(&g_bincur[b], 1);
    g_binpts[g_binstart[b] + off] = i;
}

// Warp-parallel per-bin rank sort -> deterministic ascending CSR order.
// One warp per bin: coalesced load, 32-shuffle rank, coalesced store.
__global__ void k_sortbins()
{
    int warp = (blockIdx.x * blockDim.x + threadIdx.x) >> 5;   // bin
    int lane = threadIdx.x & 31;
    if (warp >= NBIN3) return;
    int s = g_bincnt[warp] ? g_binstart[warp] : 0;
    int c = g_bincnt[warp];
    if (c <= 1) return;
    if (c <= 32) {
        int v = (lane < c) ? g_binpts[s + lane] : 0x7fffffff;
        int rank = 0;
        #pragma unroll
        for (int o = 0; o < 32; o++) {
            int u = __shfl_sync(0xffffffffu, v, o);
            rank += (u < v) || (u == v && o < lane);
        }
        if (lane < c) g_binpts[s + rank] = v;
    } else if (lane == 0) {       // rare huge bin: serial fallback
        for (int a = 1; a < c; a++) {
            int v = g_binpts[s + a]; int k = a - 1;
            while (k >= 0 && g_binpts[s + k] > v) { g_binpts[s + k + 1] = g_binpts[s + k]; k--; }
            g_binpts[s + k + 1] = v;
        }
    }
}

// ---------------------------------------------------------------------------
// Build sparse bilateral rows per bin. Candidate staging fully parallel.
// ---------------------------------------------------------------------------
__global__ void k_build()
{
    __shared__ int   sj[SCAP];
    __shared__ float s0[SCAP], s1[SCAP], s2[SCAP];
    __shared__ int   nstart[27], npre[28];
    const int tid = threadIdx.x;                       // 128
    const int b   = blockIdx.x;
    const int cnt = g_bincnt[b];
    if (cnt == 0) return;

    int b0 = b / 144, r = b - b0*144, b1 = r / 12, b2 = r - b1*12;
    int d0lo = b0 > 0 ? b0-1 : 0, d0hi = b0 < 11 ? b0+1 : 11;
    int d1lo = b1 > 0 ? b1-1 : 0, d1hi = b1 < 11 ? b1+1 : 11;
    int d2lo = b2 > 0 ? b2-1 : 0, d2hi = b2 < 11 ? b2+1 : 11;
    int n0 = d0hi-d0lo+1, n1 = d1hi-d1lo+1, n2 = d2hi-d2lo+1;
    int nseg = n0*n1*n2;                               // <= 27

    if (tid < nseg) {
        int q = tid;
        int e0 = q / (n1*n2); q -= e0*(n1*n2);
        int e1 = q / n2, e2 = q - e1*n2;
        int nbin = ((d0lo+e0)*NBIN + (d1lo+e1))*NBIN + (d2lo+e2);
        nstart[tid] = g_binstart[nbin];
        npre[tid]   = g_bincnt[nbin];
    }
    __syncthreads();
    if (tid == 0) {
        int s = 0;
        for (int k = 0; k < nseg; k++) { int c = npre[k]; npre[k] = s; s += c; }
        npre[nseg] = s;
    }
    __syncthreads();
    int tot = npre[nseg]; if (tot > SCAP) tot = SCAP;

    for (int idx = tid; idx < tot; idx += 128) {
        int seg = 0;
        while (seg + 1 < nseg && npre[seg + 1] <= idx) seg++;
        int j = g_binpts[nstart[seg] + (idx - npre[seg])];
        float4 col = g_col[j];
        sj[idx] = j;
        s0[idx] = col.x; s1[idx] = col.y; s2[idx] = col.z;
    }
    __syncthreads();

    const int lane = tid & 31;
    const int w    = tid >> 5;
    const int mybase = g_binstart[b];
    const int pos = tot;

    for (int p = w; p < cnt; p += 4) {
        int i = g_binpts[mybase + p];
        float4 ci = g_col[i];
        int iz = i >> 10, iy = (i >> 5) & 31, ix = i & 31;
        int   acc = 0;
        float nb  = 0.f;
        for (int base = 0; base < pos; base += 32) {
            int idx = base + lane;
            float ev = 1e30f; int j = 0;
            if (idx < pos) {
                j = sj[idx];
                float dz = (float)(iz - (j >> 10));
                float dy = (float)(iy - ((j >> 5) & 31));
                float dx = (float)(ix - (j & 31));
                float u3 = ci.x - s0[idx];
                float u4 = ci.y - s1[idx];
                float u5 = ci.z - s2[idx];
                ev = (dz*dz + dy*dy + dx*dx) * (SA*SA) + u3*u3 + u4*u4 + u5*u5;
            }
            bool a = (ev <= ECUT);
            unsigned m = __ballot_sync(0xffffffffu, a);
            if (a) {
                int off = acc + __popc(m & ((1u << lane) - 1u));
                if (off < CAP) {
                    float kv = __expf(-ev);
                    g_nn[i*CAP + off] = make_float2(__int_as_float(j), kv);
                    nb += kv;
                }
            }
            acc += __popc(m);
        }
        for (int o = 16; o; o >>= 1) nb += __shfl_xor_sync(0xffffffffu, nb, o);
        if (acc > CAP) acc = CAP;
        if (lane == 0) { g_ncnt[i] = acc; g_nbi[i] = nb; }
    }
}

// ---------------------------------------------------------------------------
// Iteration part A (one launch):
//   blocks [0,256):    fused z-conv + y-conv for one (z,x) column -> g_t2
//   blocks [256,598):  sparse bilateral gather (24 warps = 24 pixels each)
// ---------------------------------------------------------------------------
__global__ void k_iterA()
{
    if (blockIdx.x < 256) {
        __shared__ float t1s[32*LP];
        int z = blockIdx.x >> 5, x = blockIdx.x & 31;
        int tid = threadIdx.x;                 // 768
        int y = tid / LP, l = tid - y*LP;
        int i = (z << 10) + (y << 5) + x;
        float a = 0.f;
        #pragma unroll
        for (int zp = 0; zp < DD; zp++)
            a += g_kg[z*32 + zp] * g_qT[(((zp << 10) | (y << 5) | x))*LP + l];
        t1s[tid] = a;
        __syncthreads();
        float a2 = 0.f;
        const float* kr = &g_kg[y*32];
        #pragma unroll 8
        for (int yp = 0; yp < 32; yp++) a2 += kr[yp] * t1s[yp*LP + l];
        g_t2[i*LP + l] = a2;
    } else {
        int w    = (blockIdx.x - 256) * 24 + (threadIdx.x >> 5);
        int lane = threadIdx.x & 31;
        if (w >= NPIX || lane >= LP) return;
        int cnt  = g_ncnt[w];
        const float2* pp = &g_nn[w*CAP];
        float acc = 0.f;
        int n = 0;
        for (; n + 4 <= cnt; n += 4) {
            float2 p0 = pp[n],   p1 = pp[n+1], p2 = pp[n+2], p3 = pp[n+3];
            float a0 = g_qT[__float_as_int(p0.x)*LP + lane];
            float a1 = g_qT[__float_as_int(p1.x)*LP + lane];
            float a2 = g_qT[__float_as_int(p2.x)*LP + lane];
            float a3 = g_qT[__float_as_int(p3.x)*LP + lane];
            acc += p0.y*a0; acc += p1.y*a1; acc += p2.y*a2; acc += p3.y*a3;
        }
        for (; n < cnt; n++) { float2 p = pp[n]; acc += p.y * g_qT[__float_as_int(p.x)*LP + lane]; }
        g_bi[w*LP + lane] = acc;
    }
}

// ---------------------------------------------------------------------------
__global__ void k_final(float* __restrict__ out, int last)
{
    __shared__ float sh[32*LP];
    __shared__ float sc[32*LP];
    __shared__ float wsp[LL*LL], wbi[LL*LL];
    int z = blockIdx.x >> 5, y = blockIdx.x & 31;
    int tid = threadIdx.x;                 // 768
    int x = tid / LP, l = tid - x*LP;
    for (int e = tid; e < LL*LL; e += 768) { wsp[e] = g_CWsp[e]; wbi[e] = g_CWbi[e]; }
    int i = (z << 10) + (y << 5) + x;
    sh[tid] = g_t2[i*LP + l];
    __syncthreads();

    float sp = 0.f;
    {
        const float* kr = &g_kg[x*32];
        #pragma unroll 8
        for (int xp = 0; xp < 32; xp++) sp += kr[xp] * sh[xp*LP + l];
    }
    float nsp = g_sz[z] * g_syx[y] * g_syx[x];
    float nbi = g_nbi[i];
    __syncthreads();
    sh[tid] = sp / nsp;
    sc[tid] = g_bi[i*LP + l] / nbi;
    __syncthreads();

    float cur = -1e30f;
    if (l < LL) {
        float msg = 0.f;
        #pragma unroll
        for (int m = 0; m < LL; m++)
            msg += wsp[l*LL + m] * sh[x*LP + m] + wbi[l*LL + m] * sc[x*LP + m];
        cur = g_uT[i*LP + l] + msg;
    }
    __syncthreads();
    sh[tid] = cur;
    __syncthreads();

    float mx = -1e30f;
    #pragma unroll
    for (int m = 0; m < LL; m++) mx = fmaxf(mx, sh[x*LP + m]);
    float e = __expf(cur - mx);
    __syncthreads();
    sc[tid] = e;
    __syncthreads();
    float se = 0.f;
    #pragma unroll
    for (int m = 0; m < LL; m++) se += sc[x*LP + m];
    float q = e / se;
    g_qT[i*LP + l] = (l < LL) ? q : 0.f;
    if (last && l < LL) out[l*NPIX + i] = q;
}

// ---------------------------------------------------------------------------
extern "C" void kernel_launch(void* const* d_in, const int* in_sizes, int n_in,
                              void* d_out, int out_size)
{
    (void)in_sizes; (void)n_in; (void)out_size;
    const float* image  = (const float*)d_in[0];
    const float* logits = (const float*)d_in[1];
    const float* unary  = (const float*)d_in[2];
    const float* Wsp    = (const float*)d_in[3];
    const float* Wbi    = (const float*)d_in[4];
    const float* C      = (const float*)d_in[5];
    float* out = (float*)d_out;

    void* p_cnt = 0; void* p_cur = 0;
    cudaGetSymbolAddress(&p_cnt, g_bincnt);
    cudaGetSymbolAddress(&p_cur, g_bincur);
    cudaMemsetAsync(p_cnt, 0, NBIN3 * sizeof(int));
    cudaMemsetAsync(p_cur, 0, NBIN3 * sizeof(int));

    k_prep<<<65, 128>>>(image, logits, unary, Wsp, Wbi, C);
    k_scan<<<1, 1024>>>();
    k_scatter<<<64, 128>>>();
    k_sortbins<<<54, 1024>>>();
    k_build<<<NBIN3, 128>>>();

    for (int it = 0; it < NITER; it++) {
        k_iterA<<<598, 768>>>();
        k_final<<<256, 768>>>(out, it == NITER - 1);
    }
}